// round 5
// baseline (speedup 1.0000x reference)
#include <cuda_runtime.h>

#define N_NODES 2048
#define NGR 512
#define NGRAPH 4
#define NEDGE 32768
#define DIM 128
#define HEADS 4
#define GRID_PTS 500
#define NQ 20
#define NRG 12
#define DEGCAP 64

typedef unsigned long long ull;

// ---------------- device scratch ----------------
__device__ float g_xh[N_NODES*DIM];
__device__ float g_als[N_NODES*HEADS];
__device__ float g_ald[N_NODES*HEADS];
__device__ float g_cur1[N_NODES*DIM];
__device__ float g_cur2[N_NODES*DIM];
__device__ float g_xT [DIM*N_NODES];
__device__ float g_c1T[DIM*N_NODES];
__device__ float g_c2T[DIM*N_NODES];
__device__ int   g_cursor[N_NODES];
__device__ int   g_adjB[N_NODES*DEGCAP];
__device__ float g_pool[NRG*DIM];
__device__ float g_kf[NRG*DIM*NQ];
__device__ float g_acc[NGRAPH*32];
__device__ int   g_done;

__device__ __forceinline__ float ex2(float x){
    float y; asm("ex2.approx.ftz.f32 %0, %1;" : "=f"(y) : "f"(x)); return y;
}
__device__ __forceinline__ ull pk2(float lo, float hi){
    ull o; asm("mov.b64 %0, {%1, %2};" : "=l"(o) : "f"(lo), "f"(hi)); return o;
}
__device__ __forceinline__ void up2(float& lo, float& hi, ull v){
    asm("mov.b64 {%0, %1}, %2;" : "=f"(lo), "=f"(hi) : "l"(v));
}
__device__ __forceinline__ ull mul2(ull a, ull b){
    ull o; asm("mul.rn.f32x2 %0, %1, %2;" : "=l"(o) : "l"(a), "l"(b)); return o;
}
__device__ __forceinline__ ull add2(ull a, ull b){
    ull o; asm("add.rn.f32x2 %0, %1, %2;" : "=l"(o) : "l"(a), "l"(b)); return o;
}

// ---------------- zero counters ----------------
__global__ void k_zero(){
    int t = blockIdx.x*blockDim.x + threadIdx.x;
    if (t < N_NODES) g_cursor[t] = 0;
    if (t < NGRAPH*32) g_acc[t] = 0.f;
    if (t == 0) g_done = 0;
}

// ---------------- transpose x ----------------
__global__ void k_prep(const float* __restrict__ x){
    __shared__ float tile[32][129];
    int b = blockIdx.x, t = threadIdx.x;
    int n0 = b*32;
    #pragma unroll
    for (int i=0;i<16;i++){
        int idx = t + i*256;
        int nn = idx>>7, d = idx&127;
        tile[nn][d] = x[(size_t)(n0+nn)*DIM + d];
    }
    __syncthreads();
    #pragma unroll
    for (int i=0;i<16;i++){
        int idx = t + i*256;
        int d = idx>>5, nn = idx&31;
        g_xT[(size_t)d*N_NODES + n0 + nn] = tile[nn][d];
    }
}

// ---------------- bucketed adjacency ----------------
__global__ void k_fill(const int* __restrict__ ei){
    int e = blockIdx.x*blockDim.x + threadIdx.x;
    if (e < NEDGE){
        int d = ei[NEDGE+e];
        int pos = atomicAdd(&g_cursor[d],1);
        if (pos < DEGCAP) g_adjB[d*DEGCAP + pos] = ei[e];
    }
}

// ---------------- GAT linear: 8 nodes per block ----------------
__global__ void k_lin(const float* __restrict__ x, int layer,
                      const float* __restrict__ W,
                      const float* __restrict__ as_,
                      const float* __restrict__ ad_){
    const float* cur = layer ? g_cur1 : x;
    int b = blockIdx.x, t = threadIdx.x;
    int n0 = b*8;
    __shared__ float srow[8][128];
    #pragma unroll
    for (int i=0;i<8;i++){
        int idx = t + i*128;
        srow[idx>>7][idx&127] = cur[(size_t)n0*DIM + idx];
    }
    __syncthreads();
    float acc[8] = {0,0,0,0,0,0,0,0};
    #pragma unroll 4
    for (int k4=0;k4<32;k4++){
        float w0 = W[(k4*4+0)*DIM + t];
        float w1 = W[(k4*4+1)*DIM + t];
        float w2 = W[(k4*4+2)*DIM + t];
        float w3 = W[(k4*4+3)*DIM + t];
        #pragma unroll
        for (int j=0;j<8;j++){
            float4 sv = *(const float4*)&srow[j][k4*4];
            acc[j] = fmaf(sv.x, w0, acc[j]);
            acc[j] = fmaf(sv.y, w1, acc[j]);
            acc[j] = fmaf(sv.z, w2, acc[j]);
            acc[j] = fmaf(sv.w, w3, acc[j]);
        }
    }
    int hw = t>>5;
    float a_s = as_[t], a_d = ad_[t];
    #pragma unroll
    for (int j=0;j<8;j++){
        g_xh[(size_t)(n0+j)*DIM + t] = acc[j];
        float ps = acc[j]*a_s, pd = acc[j]*a_d;
        for (int o=16;o;o>>=1){
            ps += __shfl_xor_sync(0xffffffffu, ps, o);
            pd += __shfl_xor_sync(0xffffffffu, pd, o);
        }
        if ((t&31)==0){
            g_als[(n0+j)*HEADS + hw] = ps;
            g_ald[(n0+j)*HEADS + hw] = pd;
        }
    }
}

// ---------------- GAT attention + aggregation ----------------
__global__ void k_att(const float* __restrict__ bias, int layer){
    float* out  = layer ? g_cur2 : g_cur1;
    float* outT = layer ? g_c2T  : g_c1T;
    int relu = (layer==0);
    int n = blockIdx.x, t = threadIdx.x;
    int w = t>>5, lane = t&31;
    int deg = g_cursor[n]; if (deg > DEGCAP) deg = DEGCAP;
    int cnt = deg + 1;
    float bi = bias[t];
    __shared__ int   sadj[DEGCAP+1];
    __shared__ float sal[HEADS][DEGCAP+1];
    if (t < cnt) sadj[t] = (t < deg) ? g_adjB[n*DEGCAP + t] : n;
    __syncthreads();
    float aldn = g_ald[n*HEADS + w];
    int i0 = lane, i1 = lane+32, i2 = lane+64;
    float z0=-1e30f, z1=-1e30f, z2=-1e30f;
    if (i0 < cnt){ float z = g_als[sadj[i0]*HEADS+w] + aldn; z0 = (z>0.f)?z:0.2f*z; }
    if (i1 < cnt){ float z = g_als[sadj[i1]*HEADS+w] + aldn; z1 = (z>0.f)?z:0.2f*z; }
    if (i2 < cnt){ float z = g_als[sadj[i2]*HEADS+w] + aldn; z2 = (z>0.f)?z:0.2f*z; }
    float m = fmaxf(z0, fmaxf(z1, z2));
    #pragma unroll
    for (int o=16;o;o>>=1) m = fmaxf(m, __shfl_xor_sync(0xffffffffu,m,o));
    float e0 = (i0<cnt) ? __expf(z0-m) : 0.f;
    float e1 = (i1<cnt) ? __expf(z1-m) : 0.f;
    float e2 = (i2<cnt) ? __expf(z2-m) : 0.f;
    if (i0<cnt) sal[w][i0] = e0;
    if (i1<cnt) sal[w][i1] = e1;
    if (i2<cnt) sal[w][i2] = e2;
    float sum = e0 + e1 + e2;
    #pragma unroll
    for (int o=16;o;o>>=1) sum += __shfl_xor_sync(0xffffffffu,sum,o);
    float inv = 1.f/(sum + 1e-16f);
    __syncthreads();
    float acc = 0.f;
    int i = 0;
    for (; i+8 <= cnt; i += 8){
        float x0=g_xh[(size_t)sadj[i  ]*DIM+t], x1=g_xh[(size_t)sadj[i+1]*DIM+t];
        float x2=g_xh[(size_t)sadj[i+2]*DIM+t], x3=g_xh[(size_t)sadj[i+3]*DIM+t];
        float x4=g_xh[(size_t)sadj[i+4]*DIM+t], x5=g_xh[(size_t)sadj[i+5]*DIM+t];
        float x6=g_xh[(size_t)sadj[i+6]*DIM+t], x7=g_xh[(size_t)sadj[i+7]*DIM+t];
        acc = fmaf(sal[w][i  ],x0,acc); acc = fmaf(sal[w][i+1],x1,acc);
        acc = fmaf(sal[w][i+2],x2,acc); acc = fmaf(sal[w][i+3],x3,acc);
        acc = fmaf(sal[w][i+4],x4,acc); acc = fmaf(sal[w][i+5],x5,acc);
        acc = fmaf(sal[w][i+6],x6,acc); acc = fmaf(sal[w][i+7],x7,acc);
    }
    for (; i+4 <= cnt; i += 4){
        float x0=g_xh[(size_t)sadj[i  ]*DIM+t], x1=g_xh[(size_t)sadj[i+1]*DIM+t];
        float x2=g_xh[(size_t)sadj[i+2]*DIM+t], x3=g_xh[(size_t)sadj[i+3]*DIM+t];
        acc = fmaf(sal[w][i  ],x0,acc); acc = fmaf(sal[w][i+1],x1,acc);
        acc = fmaf(sal[w][i+2],x2,acc); acc = fmaf(sal[w][i+3],x3,acc);
    }
    for (; i < cnt; i++)
        acc = fmaf(sal[w][i], g_xh[(size_t)sadj[i]*DIM+t], acc);
    acc = fmaf(acc, inv, bi);
    if (relu) acc = fmaxf(acc, 0.f);
    out [(size_t)n*DIM + t] = acc;
    outT[(size_t)t*N_NODES + n] = acc;
}

// ---------------- fused stats + KDE density + cdf + soft quantiles ----------------
// per launch: 512 blocks (one ro group) = 4 graphs x 128 dims, one warp each.
__global__ void __launch_bounds__(32,16) k_densq(const float* __restrict__ pw, int ro){
    int b = blockIdx.x;
    int rg = ro*4 + (b >> 7), d = b & 127;
    int g = rg & 3;
    const float* baseT = (ro==0) ? g_xT : (ro==1) ? g_c1T : g_c2T;
    int lane = threadIdx.x;
    const float* row = baseT + (size_t)d*N_NODES + g*NGR;

    float v[16];
    float mn=1e30f, mx=-1e30f, s1=0.f, s2=0.f;
    #pragma unroll
    for (int i=0;i<16;i++){
        float x = row[i*32 + lane];
        v[i] = x;
        mn = fminf(mn,x); mx = fmaxf(mx,x);
        s1 += x; s2 = fmaf(x,x,s2);
    }
    #pragma unroll
    for (int o=16;o;o>>=1){
        mn = fminf(mn, __shfl_xor_sync(0xffffffffu,mn,o));
        mx = fmaxf(mx, __shfl_xor_sync(0xffffffffu,mx,o));
        s1 += __shfl_xor_sync(0xffffffffu,s1,o);
        s2 += __shfl_xor_sync(0xffffffffu,s2,o);
    }
    float mean = s1*(1.f/512.f);
    float var  = fmaxf(s2*(1.f/512.f) - mean*mean, 0.f);
    float stdv = sqrtf(var) + 3.3333333e-9f;
    float h    = 0.30440506f*stdv;                   // 1.06*512^-0.2
    float c2   = -0.72134752f/(h*h);                 // -0.5*log2(e)/h^2
    float mnA = mn - 1e-6f, mxA = mx + 1e-6f;
    float step = (mxA - mnA)*(1.f/499.f);
    float mid  = 0.5f*(mnA + mxA);
    if (lane==0) g_pool[rg*DIM + d] = pw[0]*mean + pw[1]*mx;

    __shared__ float2 sab[512];
    #pragma unroll
    for (int i=0;i<16;i++){
        float xc = v[i] - mid;
        sab[i*32 + lane] = make_float2(c2*xc*xc, -2.f*c2*xc);
    }
    __syncwarp();

    float mnc = mnA - mid;
    float g0  = fmaf((float)(lane*16), step, mnc);
    float q0  = c2*g0*g0;
    float K1  = 2.f*c2*step, K2 = c2*step*step;
    float hR  = fmaf(K1, g0, K2);
    float t1  = ex2(2.f*K2);
    float t2  = t1*t1;
    float sc  = t2*t2;
    ull s2p   = pk2(sc, sc);
    ull acc2[8];
    #pragma unroll
    for (int k=0;k<8;k++) acc2[k] = 0ull;
    for (int n=0;n<512;n++){
        float2 abv = sab[n];
        float QA  = fmaf(abv.y, g0, q0) + abv.x;
        float Ra  = fmaf(abv.y, step, hR);
        float eA  = ex2(QA);
        float rho = ex2(Ra);
        float eB  = eA*rho;
        float rA  = rho*rho*t1;
        float rB  = rA*t2;
        ull e2 = pk2(eA, eB);
        ull r2 = pk2(rA, rB);
        acc2[0] = add2(acc2[0], e2);
        #pragma unroll
        for (int k=1;k<8;k++){
            e2 = mul2(e2, r2);
            r2 = mul2(r2, s2p);
            acc2[k] = add2(acc2[k], e2);
        }
    }
    float dens[16];
    #pragma unroll
    for (int k=0;k<8;k++) up2(dens[2*k], dens[2*k+1], acc2[k]);
    int pbase = lane*16;
    #pragma unroll
    for (int j=0;j<16;j++) if (pbase + j >= GRID_PTS) dens[j] = 0.f;
    float cdfl[16];
    float run = 0.f;
    #pragma unroll
    for (int j=0;j<16;j++){ run += dens[j]; cdfl[j] = run; }
    float tot = run, xs = run;
    for (int o=1;o<32;o<<=1){ float t_=__shfl_up_sync(0xffffffffu,xs,o); if (lane>=o) xs+=t_; }
    float basev = xs - tot;
    #pragma unroll
    for (int j=0;j<16;j++) cdfl[j] += basev;
    float total = __shfl_sync(0xffffffffu, cdfl[15], 31);
    float invT  = 1.f/fmaxf(total, 1e-8f);
    float gv0 = mnA;
    #pragma unroll
    for (int j=0;j<16;j++) cdfl[j] *= invT;
    for (int q=0;q<NQ;q++){
        float qq = q*(1.f/19.f);
        float sw=0.f, swg=0.f;
        #pragma unroll
        for (int j=0;j<16;j++){
            int p = pbase + j;
            if (p < GRID_PTS){
                float dist = fabsf(cdfl[j] - qq);
                float wgt = __fdividef(1.f, 1.f + __expf(100.f*dist));
                sw += wgt;
                swg = fmaf(wgt, fmaf((float)p, step, gv0), swg);
            }
        }
        #pragma unroll
        for (int o=16;o;o>>=1){ sw  += __shfl_xor_sync(0xffffffffu,sw,o);
                                swg += __shfl_xor_sync(0xffffffffu,swg,o); }
        if (lane==0) g_kf[rg*2560 + d*NQ + q] = swg/(sw + 1e-8f);
    }
}

// ---------------- projections + (last block) final risk ----------------
__global__ void k_proj(const float* lpW0,const float* lpb0,const float* lpW1,const float* lpb1,
                       const float* lpW2,const float* lpb2,
                       const float* kW0,const float* kb0,const float* kW1,const float* kb1,
                       const float* kW2,const float* kb2,
                       const float* beta, const float* h0, float* out){
    int rg = blockIdx.x; int g = rg&3; int ro = rg>>2;
    const float* lpW = (ro==0)?lpW0:(ro==1)?lpW1:lpW2;
    const float* lpb = (ro==0)?lpb0:(ro==1)?lpb1:lpb2;
    const float* kW  = (ro==0)?kW0 :(ro==1)?kW1 :kW2;
    const float* kb  = (ro==0)?kb0 :(ro==1)?kb1 :kb2;
    int t = threadIdx.x; int o = t&31, seg = t>>5;
    const float* kf = &g_kf[rg*2560];
    float kp = 0.f;
    for (int i=seg*320; i<seg*320+320; i++)
        kp = fmaf(kf[i], kW[i*32 + o], kp);
    const float* wp = &g_pool[rg*DIM];
    float hp = 0.f;
    for (int dd=seg*16; dd<seg*16+16; dd++)
        hp = fmaf(wp[dd], lpW[dd*32 + o], hp);
    __shared__ float r1[256], r2s[256];
    __shared__ int slast;
    r1[t]=kp; r2s[t]=hp; __syncthreads();
    if (t < 32){
        float ks=0.f, hs=0.f;
        for (int s=0;s<8;s++){ ks += r1[t + s*32]; hs += r2s[t + s*32]; }
        float val = (ks + kb[t]) + (hs + lpb[t]);
        atomicAdd(&g_acc[g*32 + t], val*(1.f/3.f));
    }
    __threadfence();
    __syncthreads();
    if (t == 0){
        int prev = atomicAdd(&g_done, 1);
        slast = (prev == NRG-1);
    }
    __syncthreads();
    if (slast && t < 128){
        __threadfence();
        int gg = t>>5, oo = t&31;
        float vv = g_acc[gg*32 + oo]*beta[oo];
        #pragma unroll
        for (int ofs=16; ofs; ofs>>=1) vv += __shfl_xor_sync(0xffffffffu, vv, ofs);
        if (oo==0) out[gg] = vv + h0[0];
    }
}

// ---------------- launch (multi-stream fork/join, graph-capturable) ----------------
extern "C" void kernel_launch(void* const* d_in, const int* in_sizes, int n_in,
                              void* d_out, int out_size){
    const float* x   = (const float*)d_in[0];
    const int*   ei  = (const int*)d_in[1];
    const float* W0  = (const float*)d_in[3];
    const float* as0 = (const float*)d_in[4];
    const float* ad0 = (const float*)d_in[5];
    const float* b0  = (const float*)d_in[6];
    const float* W1  = (const float*)d_in[7];
    const float* as1 = (const float*)d_in[8];
    const float* ad1 = (const float*)d_in[9];
    const float* b1  = (const float*)d_in[10];
    const float* lpW0=(const float*)d_in[11]; const float* lpb0=(const float*)d_in[12];
    const float* lpW1=(const float*)d_in[13]; const float* lpb1=(const float*)d_in[14];
    const float* lpW2=(const float*)d_in[15]; const float* lpb2=(const float*)d_in[16];
    const float* kW0 =(const float*)d_in[17]; const float* kb0 =(const float*)d_in[18];
    const float* kW1 =(const float*)d_in[19]; const float* kb1 =(const float*)d_in[20];
    const float* kW2 =(const float*)d_in[21]; const float* kb2 =(const float*)d_in[22];
    const float* poolw=(const float*)d_in[23];
    const float* beta =(const float*)d_in[24];
    const float* h0   =(const float*)d_in[25];
    float* out = (float*)d_out;

    // streams/events created once (first call is the uncaptured correctness run)
    static cudaStream_t sA = nullptr, sB = nullptr;
    static cudaEvent_t evStart, evFill, evAtt0, evD1, evD2;
    if (!sA){
        cudaStreamCreateWithFlags(&sA, cudaStreamNonBlocking);
        cudaStreamCreateWithFlags(&sB, cudaStreamNonBlocking);
        cudaEventCreateWithFlags(&evStart, cudaEventDisableTiming);
        cudaEventCreateWithFlags(&evFill,  cudaEventDisableTiming);
        cudaEventCreateWithFlags(&evAtt0,  cudaEventDisableTiming);
        cudaEventCreateWithFlags(&evD1,    cudaEventDisableTiming);
        cudaEventCreateWithFlags(&evD2,    cudaEventDisableTiming);
    }

    cudaEventRecord(evStart, 0);

    // stream A: zero -> fill (adjacency), later densq(ro=1)
    cudaStreamWaitEvent(sA, evStart, 0);
    k_zero<<<8, 256, 0, sA>>>();
    k_fill<<<64, 512, 0, sA>>>(ei);
    cudaEventRecord(evFill, sA);

    // stream B: lin0 -> att0 -> lin1 -> att1 -> densq(ro=2)
    cudaStreamWaitEvent(sB, evStart, 0);
    k_lin<<<256, 128, 0, sB>>>(x, 0, W0, as0, ad0);
    cudaStreamWaitEvent(sB, evFill, 0);
    k_att<<<N_NODES, 128, 0, sB>>>(b0, 0);
    cudaEventRecord(evAtt0, sB);
    k_lin<<<256, 128, 0, sB>>>(x, 1, W1, as1, ad1);
    k_att<<<N_NODES, 128, 0, sB>>>(b1, 1);
    k_densq<<<512, 32, 0, sB>>>(poolw, 2);
    cudaEventRecord(evD2, sB);

    // stream 0: transpose x, densq(ro=0) — overlaps the whole GAT chain
    k_prep<<<64, 256>>>(x);
    k_densq<<<512, 32>>>(poolw, 0);

    // stream A: densq(ro=1) after att0
    cudaStreamWaitEvent(sA, evAtt0, 0);
    k_densq<<<512, 32, 0, sA>>>(poolw, 1);
    cudaEventRecord(evD1, sA);

    // join on stream 0
    cudaStreamWaitEvent(0, evD1, 0);
    cudaStreamWaitEvent(0, evD2, 0);
    k_proj<<<NRG, 256>>>(lpW0,lpb0,lpW1,lpb1,lpW2,lpb2,
                         kW0,kb0,kW1,kb1,kW2,kb2, beta, h0, out);
}

// round 6
// speedup vs baseline: 1.0771x; 1.0771x over previous
#include <cuda_runtime.h>

#define N_NODES 2048
#define NGR 512
#define NGRAPH 4
#define NEDGE 32768
#define DIM 128
#define HEADS 4
#define GRID_PTS 500
#define NQ 20
#define NRG 12
#define DEGCAP 64

typedef unsigned long long ull;

// ---------------- device scratch ----------------
__device__ float g_xh[N_NODES*DIM];
__device__ float g_als[N_NODES*HEADS];
__device__ float g_ald[N_NODES*HEADS];
__device__ float g_cur1[N_NODES*DIM];
__device__ float g_cur2[N_NODES*DIM];
__device__ float g_xT [DIM*N_NODES];
__device__ float g_c1T[DIM*N_NODES];
__device__ float g_c2T[DIM*N_NODES];
__device__ int   g_cursor[N_NODES];
__device__ int   g_adjB[N_NODES*DEGCAP];
__device__ float g_pool[NRG*DIM];
__device__ float g_kf[NRG*DIM*NQ];
__device__ float g_acc[NGRAPH*32];
__device__ int   g_done;

__device__ __forceinline__ float ex2(float x){
    float y; asm("ex2.approx.ftz.f32 %0, %1;" : "=f"(y) : "f"(x)); return y;
}
__device__ __forceinline__ ull pk2(float lo, float hi){
    ull o; asm("mov.b64 %0, {%1, %2};" : "=l"(o) : "f"(lo), "f"(hi)); return o;
}
__device__ __forceinline__ void up2(float& lo, float& hi, ull v){
    asm("mov.b64 {%0, %1}, %2;" : "=f"(lo), "=f"(hi) : "l"(v));
}
__device__ __forceinline__ ull mul2(ull a, ull b){
    ull o; asm("mul.rn.f32x2 %0, %1, %2;" : "=l"(o) : "l"(a), "l"(b)); return o;
}
__device__ __forceinline__ ull add2(ull a, ull b){
    ull o; asm("add.rn.f32x2 %0, %1, %2;" : "=l"(o) : "l"(a), "l"(b)); return o;
}

// ---------------- prep: zero counters + transpose x ----------------
__global__ void k_prep(const float* __restrict__ x){
    __shared__ float tile[32][129];
    int b = blockIdx.x, t = threadIdx.x;
    int n0 = b*32;
    int gt = b*256 + t;
    if (gt < N_NODES) g_cursor[gt] = 0;
    if (gt < NGRAPH*32) g_acc[gt] = 0.f;
    if (gt == 0) g_done = 0;
    #pragma unroll
    for (int i=0;i<16;i++){
        int idx = t + i*256;
        int nn = idx>>7, d = idx&127;
        tile[nn][d] = x[(size_t)(n0+nn)*DIM + d];
    }
    __syncthreads();
    #pragma unroll
    for (int i=0;i<16;i++){
        int idx = t + i*256;
        int d = idx>>5, nn = idx&31;
        g_xT[(size_t)d*N_NODES + n0 + nn] = tile[nn][d];
    }
}

// ---------------- bucketed adjacency ----------------
__global__ void k_fill(const int* __restrict__ ei){
    int e = blockIdx.x*blockDim.x + threadIdx.x;
    if (e < NEDGE){
        int d = ei[NEDGE+e];
        int pos = atomicAdd(&g_cursor[d],1);
        if (pos < DEGCAP) g_adjB[d*DEGCAP + pos] = ei[e];
    }
}

// ---------------- GAT linear: 8 nodes per block ----------------
__global__ void k_lin(const float* __restrict__ x, int layer,
                      const float* __restrict__ W,
                      const float* __restrict__ as_,
                      const float* __restrict__ ad_){
    const float* cur = layer ? g_cur1 : x;
    int b = blockIdx.x, t = threadIdx.x;
    int n0 = b*8;
    __shared__ float srow[8][128];
    #pragma unroll
    for (int i=0;i<8;i++){
        int idx = t + i*128;
        srow[idx>>7][idx&127] = cur[(size_t)n0*DIM + idx];
    }
    __syncthreads();
    float acc[8] = {0,0,0,0,0,0,0,0};
    #pragma unroll 4
    for (int k4=0;k4<32;k4++){
        float w0 = W[(k4*4+0)*DIM + t];
        float w1 = W[(k4*4+1)*DIM + t];
        float w2 = W[(k4*4+2)*DIM + t];
        float w3 = W[(k4*4+3)*DIM + t];
        #pragma unroll
        for (int j=0;j<8;j++){
            float4 sv = *(const float4*)&srow[j][k4*4];
            acc[j] = fmaf(sv.x, w0, acc[j]);
            acc[j] = fmaf(sv.y, w1, acc[j]);
            acc[j] = fmaf(sv.z, w2, acc[j]);
            acc[j] = fmaf(sv.w, w3, acc[j]);
        }
    }
    int hw = t>>5;
    float a_s = as_[t], a_d = ad_[t];
    #pragma unroll
    for (int j=0;j<8;j++){
        g_xh[(size_t)(n0+j)*DIM + t] = acc[j];
        float ps = acc[j]*a_s, pd = acc[j]*a_d;
        for (int o=16;o;o>>=1){
            ps += __shfl_xor_sync(0xffffffffu, ps, o);
            pd += __shfl_xor_sync(0xffffffffu, pd, o);
        }
        if ((t&31)==0){
            g_als[(n0+j)*HEADS + hw] = ps;
            g_ald[(n0+j)*HEADS + hw] = pd;
        }
    }
}

// ---------------- GAT attention + aggregation ----------------
__global__ void k_att(const float* __restrict__ bias, int layer){
    float* out  = layer ? g_cur2 : g_cur1;
    float* outT = layer ? g_c2T  : g_c1T;
    int relu = (layer==0);
    int n = blockIdx.x, t = threadIdx.x;
    int w = t>>5, lane = t&31;
    int deg = g_cursor[n]; if (deg > DEGCAP) deg = DEGCAP;
    int cnt = deg + 1;
    float bi = bias[t];
    __shared__ int   sadj[DEGCAP+1];
    __shared__ float sal[HEADS][DEGCAP+1];
    if (t < cnt) sadj[t] = (t < deg) ? g_adjB[n*DEGCAP + t] : n;
    __syncthreads();
    float aldn = g_ald[n*HEADS + w];
    int i0 = lane, i1 = lane+32, i2 = lane+64;
    float z0=-1e30f, z1=-1e30f, z2=-1e30f;
    if (i0 < cnt){ float z = g_als[sadj[i0]*HEADS+w] + aldn; z0 = (z>0.f)?z:0.2f*z; }
    if (i1 < cnt){ float z = g_als[sadj[i1]*HEADS+w] + aldn; z1 = (z>0.f)?z:0.2f*z; }
    if (i2 < cnt){ float z = g_als[sadj[i2]*HEADS+w] + aldn; z2 = (z>0.f)?z:0.2f*z; }
    float m = fmaxf(z0, fmaxf(z1, z2));
    #pragma unroll
    for (int o=16;o;o>>=1) m = fmaxf(m, __shfl_xor_sync(0xffffffffu,m,o));
    float e0 = (i0<cnt) ? __expf(z0-m) : 0.f;
    float e1 = (i1<cnt) ? __expf(z1-m) : 0.f;
    float e2 = (i2<cnt) ? __expf(z2-m) : 0.f;
    if (i0<cnt) sal[w][i0] = e0;
    if (i1<cnt) sal[w][i1] = e1;
    if (i2<cnt) sal[w][i2] = e2;
    float sum = e0 + e1 + e2;
    #pragma unroll
    for (int o=16;o;o>>=1) sum += __shfl_xor_sync(0xffffffffu,sum,o);
    float inv = 1.f/(sum + 1e-16f);
    __syncthreads();
    float acc = 0.f;
    int i = 0;
    for (; i+8 <= cnt; i += 8){
        float x0=g_xh[(size_t)sadj[i  ]*DIM+t], x1=g_xh[(size_t)sadj[i+1]*DIM+t];
        float x2=g_xh[(size_t)sadj[i+2]*DIM+t], x3=g_xh[(size_t)sadj[i+3]*DIM+t];
        float x4=g_xh[(size_t)sadj[i+4]*DIM+t], x5=g_xh[(size_t)sadj[i+5]*DIM+t];
        float x6=g_xh[(size_t)sadj[i+6]*DIM+t], x7=g_xh[(size_t)sadj[i+7]*DIM+t];
        acc = fmaf(sal[w][i  ],x0,acc); acc = fmaf(sal[w][i+1],x1,acc);
        acc = fmaf(sal[w][i+2],x2,acc); acc = fmaf(sal[w][i+3],x3,acc);
        acc = fmaf(sal[w][i+4],x4,acc); acc = fmaf(sal[w][i+5],x5,acc);
        acc = fmaf(sal[w][i+6],x6,acc); acc = fmaf(sal[w][i+7],x7,acc);
    }
    for (; i+4 <= cnt; i += 4){
        float x0=g_xh[(size_t)sadj[i  ]*DIM+t], x1=g_xh[(size_t)sadj[i+1]*DIM+t];
        float x2=g_xh[(size_t)sadj[i+2]*DIM+t], x3=g_xh[(size_t)sadj[i+3]*DIM+t];
        acc = fmaf(sal[w][i  ],x0,acc); acc = fmaf(sal[w][i+1],x1,acc);
        acc = fmaf(sal[w][i+2],x2,acc); acc = fmaf(sal[w][i+3],x3,acc);
    }
    for (; i < cnt; i++)
        acc = fmaf(sal[w][i], g_xh[(size_t)sadj[i]*DIM+t], acc);
    acc = fmaf(acc, inv, bi);
    if (relu) acc = fmaxf(acc, 0.f);
    out [(size_t)n*DIM + t] = acc;
    outT[(size_t)t*N_NODES + n] = acc;
}

// ---------------- fused stats + KDE density + cdf + soft quantiles ----------------
// 512 blocks per launch (one ro), 64 threads = 2 warps per (g,d).
// Warp w covers nodes [w*256, w*256+256), ILP-2 inside. Quantiles split 10/10.
__global__ void __launch_bounds__(64) k_densq(const float* __restrict__ pw, int ro){
    int b = blockIdx.x;
    int rg = ro*4 + (b >> 7), d = b & 127;
    int g = rg & 3;
    const float* baseT = (ro==0) ? g_xT : (ro==1) ? g_c1T : g_c2T;
    int t = threadIdx.x, w = t>>5, lane = t&31;
    const float* row = baseT + (size_t)d*N_NODES + g*NGR + w*256;

    // stats: 8 values per lane per warp (each warp covers 256 nodes)
    float v[8];
    float mn=1e30f, mx=-1e30f, s1=0.f, s2=0.f;
    #pragma unroll
    for (int i=0;i<8;i++){
        float x = row[i*32 + lane];
        v[i] = x;
        mn = fminf(mn,x); mx = fmaxf(mx,x);
        s1 += x; s2 = fmaf(x,x,s2);
    }
    #pragma unroll
    for (int o=16;o;o>>=1){
        mn = fminf(mn, __shfl_xor_sync(0xffffffffu,mn,o));
        mx = fmaxf(mx, __shfl_xor_sync(0xffffffffu,mx,o));
        s1 += __shfl_xor_sync(0xffffffffu,s1,o);
        s2 += __shfl_xor_sync(0xffffffffu,s2,o);
    }
    __shared__ float sred[2][4];
    if (lane==0){ sred[w][0]=mn; sred[w][1]=mx; sred[w][2]=s1; sred[w][3]=s2; }
    __syncthreads();
    mn = fminf(sred[0][0], sred[1][0]);
    mx = fmaxf(sred[0][1], sred[1][1]);
    s1 = sred[0][2] + sred[1][2];
    s2 = sred[0][3] + sred[1][3];

    float mean = s1*(1.f/512.f);
    float var  = fmaxf(s2*(1.f/512.f) - mean*mean, 0.f);
    float stdv = sqrtf(var) + 3.3333333e-9f;
    float h    = 0.30440506f*stdv;                   // 1.06*512^-0.2
    float c2   = -0.72134752f/(h*h);                 // -0.5*log2(e)/h^2
    float mnA = mn - 1e-6f, mxA = mx + 1e-6f;
    float step = (mxA - mnA)*(1.f/499.f);
    float mid  = 0.5f*(mnA + mxA);
    if (t==0) g_pool[rg*DIM + d] = pw[0]*mean + pw[1]*mx;

    __shared__ float2 sab[512];
    #pragma unroll
    for (int i=0;i<8;i++){
        float xc = v[i] - mid;
        sab[w*256 + i*32 + lane] = make_float2(c2*xc*xc, -2.f*c2*xc);
    }
    __syncthreads();

    // density chains: lane -> points [lane*16, lane*16+16), 2 nodes per iter (ILP-2)
    float mnc = mnA - mid;
    float g0  = fmaf((float)(lane*16), step, mnc);
    float q0  = c2*g0*g0;
    float K1  = 2.f*c2*step, K2 = c2*step*step;
    float hR  = fmaf(K1, g0, K2);
    float t1  = ex2(2.f*K2);
    float t2  = t1*t1;
    float sc  = t2*t2;
    ull s2p   = pk2(sc, sc);
    ull acc2[8];
    #pragma unroll
    for (int k=0;k<8;k++) acc2[k] = 0ull;
    const float2* abp = sab + w*256;
    for (int n=0;n<128;n++){
        float2 A = abp[n];
        float2 B = abp[n+128];
        float QAa = fmaf(A.y, g0, q0) + A.x;
        float QAb = fmaf(B.y, g0, q0) + B.x;
        float Raa = fmaf(A.y, step, hR);
        float Rab = fmaf(B.y, step, hR);
        float eAa = ex2(QAa), eAb = ex2(QAb);
        float ra  = ex2(Raa), rb  = ex2(Rab);
        float eBa = eAa*ra,  eBb = eAb*rb;
        float rAa = ra*ra*t1, rAb = rb*rb*t1;
        float rBa = rAa*t2,  rBb = rAb*t2;
        ull e2a = pk2(eAa, eBa), r2a = pk2(rAa, rBa);
        ull e2b = pk2(eAb, eBb), r2b = pk2(rAb, rBb);
        acc2[0] = add2(acc2[0], add2(e2a, e2b));
        #pragma unroll
        for (int k=1;k<8;k++){
            e2a = mul2(e2a, r2a);
            e2b = mul2(e2b, r2b);
            r2a = mul2(r2a, s2p);
            r2b = mul2(r2b, s2p);
            acc2[k] = add2(acc2[k], add2(e2a, e2b));
        }
    }
    // combine warp partials via smem
    __shared__ float sdens[2][512];
    float dens[16];
    #pragma unroll
    for (int k=0;k<8;k++) up2(dens[2*k], dens[2*k+1], acc2[k]);
    int pbase = lane*16;
    #pragma unroll
    for (int j=0;j<16;j++) sdens[w][pbase+j] = dens[j];
    __syncthreads();
    #pragma unroll
    for (int j=0;j<16;j++){
        dens[j] = sdens[0][pbase+j] + sdens[1][pbase+j];
        if (pbase + j >= GRID_PTS) dens[j] = 0.f;
    }
    // cdf (both warps, redundant)
    float cdfl[16];
    float run = 0.f;
    #pragma unroll
    for (int j=0;j<16;j++){ run += dens[j]; cdfl[j] = run; }
    float tot = run, xs = run;
    for (int o=1;o<32;o<<=1){ float t_=__shfl_up_sync(0xffffffffu,xs,o); if (lane>=o) xs+=t_; }
    float basev = xs - tot;
    #pragma unroll
    for (int j=0;j<16;j++) cdfl[j] += basev;
    float total = __shfl_sync(0xffffffffu, cdfl[15], 31);
    float invT  = 1.f/fmaxf(total, 1e-8f);
    float gv0 = mnA;
    #pragma unroll
    for (int j=0;j<16;j++) cdfl[j] *= invT;
    // quantiles: warp0 -> q 0..9, warp1 -> q 10..19
    for (int qi=0; qi<NQ/2; qi++){
        int q = w*(NQ/2) + qi;
        float qq = q*(1.f/19.f);
        float sw=0.f, swg=0.f;
        #pragma unroll
        for (int j=0;j<16;j++){
            int p = pbase + j;
            if (p < GRID_PTS){
                float dist = fabsf(cdfl[j] - qq);
                float wgt = __fdividef(1.f, 1.f + __expf(100.f*dist));
                sw += wgt;
                swg = fmaf(wgt, fmaf((float)p, step, gv0), swg);
            }
        }
        #pragma unroll
        for (int o=16;o;o>>=1){ sw  += __shfl_xor_sync(0xffffffffu,sw,o);
                                swg += __shfl_xor_sync(0xffffffffu,swg,o); }
        if (lane==0) g_kf[rg*2560 + d*NQ + q] = swg/(sw + 1e-8f);
    }
}

// ---------------- projections + (last block) final risk ----------------
__global__ void k_proj(const float* lpW0,const float* lpb0,const float* lpW1,const float* lpb1,
                       const float* lpW2,const float* lpb2,
                       const float* kW0,const float* kb0,const float* kW1,const float* kb1,
                       const float* kW2,const float* kb2,
                       const float* beta, const float* h0, float* out){
    int rg = blockIdx.x; int g = rg&3; int ro = rg>>2;
    const float* lpW = (ro==0)?lpW0:(ro==1)?lpW1:lpW2;
    const float* lpb = (ro==0)?lpb0:(ro==1)?lpb1:lpb2;
    const float* kW  = (ro==0)?kW0 :(ro==1)?kW1 :kW2;
    const float* kb  = (ro==0)?kb0 :(ro==1)?kb1 :kb2;
    int t = threadIdx.x; int o = t&31, seg = t>>5;
    const float* kf = &g_kf[rg*2560];
    float kp = 0.f;
    for (int i=seg*320; i<seg*320+320; i++)
        kp = fmaf(kf[i], kW[i*32 + o], kp);
    const float* wp = &g_pool[rg*DIM];
    float hp = 0.f;
    for (int dd=seg*16; dd<seg*16+16; dd++)
        hp = fmaf(wp[dd], lpW[dd*32 + o], hp);
    __shared__ float r1[256], r2s[256];
    __shared__ int slast;
    r1[t]=kp; r2s[t]=hp; __syncthreads();
    if (t < 32){
        float ks=0.f, hs=0.f;
        for (int s=0;s<8;s++){ ks += r1[t + s*32]; hs += r2s[t + s*32]; }
        float val = (ks + kb[t]) + (hs + lpb[t]);
        atomicAdd(&g_acc[g*32 + t], val*(1.f/3.f));
    }
    __threadfence();
    __syncthreads();
    if (t == 0){
        int prev = atomicAdd(&g_done, 1);
        slast = (prev == NRG-1);
    }
    __syncthreads();
    if (slast && t < 128){
        __threadfence();
        int gg = t>>5, oo = t&31;
        float vv = g_acc[gg*32 + oo]*beta[oo];
        #pragma unroll
        for (int ofs=16; ofs; ofs>>=1) vv += __shfl_xor_sync(0xffffffffu, vv, ofs);
        if (oo==0) out[gg] = vv + h0[0];
    }
}

// ---------------- launch (single stream) ----------------
extern "C" void kernel_launch(void* const* d_in, const int* in_sizes, int n_in,
                              void* d_out, int out_size){
    const float* x   = (const float*)d_in[0];
    const int*   ei  = (const int*)d_in[1];
    const float* W0  = (const float*)d_in[3];
    const float* as0 = (const float*)d_in[4];
    const float* ad0 = (const float*)d_in[5];
    const float* b0  = (const float*)d_in[6];
    const float* W1  = (const float*)d_in[7];
    const float* as1 = (const float*)d_in[8];
    const float* ad1 = (const float*)d_in[9];
    const float* b1  = (const float*)d_in[10];
    const float* lpW0=(const float*)d_in[11]; const float* lpb0=(const float*)d_in[12];
    const float* lpW1=(const float*)d_in[13]; const float* lpb1=(const float*)d_in[14];
    const float* lpW2=(const float*)d_in[15]; const float* lpb2=(const float*)d_in[16];
    const float* kW0 =(const float*)d_in[17]; const float* kb0 =(const float*)d_in[18];
    const float* kW1 =(const float*)d_in[19]; const float* kb1 =(const float*)d_in[20];
    const float* kW2 =(const float*)d_in[21]; const float* kb2 =(const float*)d_in[22];
    const float* poolw=(const float*)d_in[23];
    const float* beta =(const float*)d_in[24];
    const float* h0   =(const float*)d_in[25];
    float* out = (float*)d_out;

    k_prep<<<64, 256>>>(x);
    k_fill<<<64, 512>>>(ei);

    k_lin<<<256, 128>>>(x, 0, W0, as0, ad0);
    k_att<<<N_NODES, 128>>>(b0, 0);
    k_lin<<<256, 128>>>(x, 1, W1, as1, ad1);
    k_att<<<N_NODES, 128>>>(b1, 1);

    k_densq<<<512, 64>>>(poolw, 0);
    k_densq<<<512, 64>>>(poolw, 1);
    k_densq<<<512, 64>>>(poolw, 2);
    k_proj <<<NRG, 256>>>(lpW0,lpb0,lpW1,lpb1,lpW2,lpb2,
                          kW0,kb0,kW1,kb1,kW2,kb2, beta, h0, out);
}

// round 7
// speedup vs baseline: 1.2735x; 1.1823x over previous
#include <cuda_runtime.h>

#define N_NODES 2048
#define NGR 512
#define NGRAPH 4
#define NEDGE 32768
#define DIM 128
#define HEADS 4
#define GRID_PTS 500
#define NQ 20
#define NRG 12
#define DEGCAP 64
#define NBLK 148
#define NTHR 512

typedef unsigned long long ull;

// ---------------- device scratch ----------------
__device__ float g_xh[N_NODES*DIM];
__device__ float g_als[N_NODES*HEADS];
__device__ float g_ald[N_NODES*HEADS];
__device__ float g_cur1[N_NODES*DIM];
__device__ float g_xT [DIM*N_NODES];
__device__ float g_c1T[DIM*N_NODES];
__device__ float g_c2T[DIM*N_NODES];
__device__ int   g_cursor[N_NODES];      // zero-init; re-zeroed at end of every run
__device__ int   g_adjB[N_NODES*DEGCAP];
__device__ float g_pool[NRG*DIM];
__device__ float g_kf[NRG*DIM*NQ];
__device__ float g_acc[NGRAPH*32];
__device__ int   g_done;
__device__ unsigned g_barCnt;
__device__ volatile unsigned g_barGen;

__device__ __forceinline__ float ex2(float x){
    float y; asm("ex2.approx.ftz.f32 %0, %1;" : "=f"(y) : "f"(x)); return y;
}
__device__ __forceinline__ ull pk2(float lo, float hi){
    ull o; asm("mov.b64 %0, {%1, %2};" : "=l"(o) : "f"(lo), "f"(hi)); return o;
}
__device__ __forceinline__ void up2(float& lo, float& hi, ull v){
    asm("mov.b64 {%0, %1}, %2;" : "=f"(lo), "=f"(hi) : "l"(v));
}
__device__ __forceinline__ ull mul2(ull a, ull b){
    ull o; asm("mul.rn.f32x2 %0, %1, %2;" : "=l"(o) : "l"(a), "l"(b)); return o;
}
__device__ __forceinline__ ull add2(ull a, ull b){
    ull o; asm("add.rn.f32x2 %0, %1, %2;" : "=l"(o) : "l"(a), "l"(b)); return o;
}

// grid-wide barrier: generation-based; gpu-scope fences flush L1 (sm_103a CCTL.IVALL)
__device__ __forceinline__ void grid_sync(){
    __syncthreads();
    if (threadIdx.x == 0){
        __threadfence();
        unsigned gen = g_barGen;
        if (atomicAdd(&g_barCnt, 1u) == (unsigned)(NBLK-1)){
            atomicExch(&g_barCnt, 0u);
            __threadfence();
            g_barGen = gen + 1u;
        } else {
            while (g_barGen == gen) __nanosleep(32);
        }
        __threadfence();
    }
    __syncthreads();
}

#define GROUP_BAR(gid) asm volatile("bar.sync %0, %1;" :: "r"((gid)+4), "r"(128) : "memory")

// ---------------- phase: linear (xh = cur @ W, attention logits) ----------------
__device__ void lin_phase(const float* __restrict__ cur,
                          const float* __restrict__ W,
                          const float* __restrict__ as_,
                          const float* __restrict__ ad_,
                          int b, int tid, char* smem){
    int g = tid>>7, gt = tid&127;
    int tI = g*NBLK + b;                       // tile of 8 nodes
    bool act = (tI < N_NODES/8);
    float (*srow)[128] = (float(*)[128])(smem + g*4096);
    int n0 = tI*8;
    if (act){
        #pragma unroll
        for (int i=0;i<8;i++){
            int idx = gt + i*128;
            srow[idx>>7][idx&127] = cur[(size_t)n0*DIM + idx];
        }
    }
    GROUP_BAR(g);
    if (act){
        float acc[8] = {0,0,0,0,0,0,0,0};
        #pragma unroll 4
        for (int k4=0;k4<32;k4++){
            float w0 = W[(k4*4+0)*DIM + gt];
            float w1 = W[(k4*4+1)*DIM + gt];
            float w2 = W[(k4*4+2)*DIM + gt];
            float w3 = W[(k4*4+3)*DIM + gt];
            #pragma unroll
            for (int j=0;j<8;j++){
                float4 sv = *(const float4*)&srow[j][k4*4];
                acc[j] = fmaf(sv.x, w0, acc[j]);
                acc[j] = fmaf(sv.y, w1, acc[j]);
                acc[j] = fmaf(sv.z, w2, acc[j]);
                acc[j] = fmaf(sv.w, w3, acc[j]);
            }
        }
        int hw = gt>>5;
        float a_s = as_[gt], a_d = ad_[gt];
        #pragma unroll
        for (int j=0;j<8;j++){
            g_xh[(size_t)(n0+j)*DIM + gt] = acc[j];
            float ps = acc[j]*a_s, pd = acc[j]*a_d;
            #pragma unroll
            for (int o=16;o;o>>=1){
                ps += __shfl_xor_sync(0xffffffffu, ps, o);
                pd += __shfl_xor_sync(0xffffffffu, pd, o);
            }
            if ((gt&31)==0){
                g_als[(n0+j)*HEADS + hw] = ps;
                g_ald[(n0+j)*HEADS + hw] = pd;
            }
        }
    }
}

// ---------------- phase: GAT attention + aggregation ----------------
__device__ void att_phase(const float* __restrict__ bias, int layer,
                          int b, int tid, char* smem){
    int g = tid>>7, gt = tid&127;
    int w4 = gt>>5, lane = gt&31;
    char* base = smem + g*1408;
    int* sadj = (int*)base;                         // 68 ints
    float (*sal)[68] = (float(*)[68])(base + 272);  // [4][68]
    float* outT = layer ? g_c2T : g_c1T;
    float bi = bias[gt];
    for (int iter=0; iter<4; iter++){
        int n = iter*592 + b*4 + g;
        bool act = (n < N_NODES);
        int deg = 0, cnt = 1;
        if (act){
            deg = g_cursor[n]; if (deg > DEGCAP) deg = DEGCAP;
            cnt = deg + 1;
            if (gt < cnt) sadj[gt] = (gt < deg) ? g_adjB[n*DEGCAP + gt] : n;
        }
        GROUP_BAR(g);
        if (act){
            float aldn = g_ald[n*HEADS + w4];
            int i0 = lane, i1 = lane+32, i2 = lane+64;
            float z0=-1e30f, z1=-1e30f, z2=-1e30f;
            if (i0 < cnt){ float z = g_als[sadj[i0]*HEADS+w4] + aldn; z0 = (z>0.f)?z:0.2f*z; }
            if (i1 < cnt){ float z = g_als[sadj[i1]*HEADS+w4] + aldn; z1 = (z>0.f)?z:0.2f*z; }
            if (i2 < cnt){ float z = g_als[sadj[i2]*HEADS+w4] + aldn; z2 = (z>0.f)?z:0.2f*z; }
            float m = fmaxf(z0, fmaxf(z1, z2));
            #pragma unroll
            for (int o=16;o;o>>=1) m = fmaxf(m, __shfl_xor_sync(0xffffffffu,m,o));
            float e0 = (i0<cnt) ? __expf(z0-m) : 0.f;
            float e1 = (i1<cnt) ? __expf(z1-m) : 0.f;
            float e2 = (i2<cnt) ? __expf(z2-m) : 0.f;
            if (i0<cnt) sal[w4][i0] = e0;
            if (i1<cnt) sal[w4][i1] = e1;
            if (i2<cnt) sal[w4][i2] = e2;
            float sum = e0 + e1 + e2;
            #pragma unroll
            for (int o=16;o;o>>=1) sum += __shfl_xor_sync(0xffffffffu,sum,o);
            float inv = 1.f/(sum + 1e-16f);
            __syncwarp();
            float acc = 0.f;
            int i = 0;
            for (; i+8 <= cnt; i += 8){
                float x0=g_xh[(size_t)sadj[i  ]*DIM+gt], x1=g_xh[(size_t)sadj[i+1]*DIM+gt];
                float x2=g_xh[(size_t)sadj[i+2]*DIM+gt], x3=g_xh[(size_t)sadj[i+3]*DIM+gt];
                float x4=g_xh[(size_t)sadj[i+4]*DIM+gt], x5=g_xh[(size_t)sadj[i+5]*DIM+gt];
                float x6=g_xh[(size_t)sadj[i+6]*DIM+gt], x7=g_xh[(size_t)sadj[i+7]*DIM+gt];
                acc = fmaf(sal[w4][i  ],x0,acc); acc = fmaf(sal[w4][i+1],x1,acc);
                acc = fmaf(sal[w4][i+2],x2,acc); acc = fmaf(sal[w4][i+3],x3,acc);
                acc = fmaf(sal[w4][i+4],x4,acc); acc = fmaf(sal[w4][i+5],x5,acc);
                acc = fmaf(sal[w4][i+6],x6,acc); acc = fmaf(sal[w4][i+7],x7,acc);
            }
            for (; i < cnt; i++)
                acc = fmaf(sal[w4][i], g_xh[(size_t)sadj[i]*DIM+gt], acc);
            acc = fmaf(acc, inv, bi);
            if (layer==0){
                acc = fmaxf(acc, 0.f);
                g_cur1[(size_t)n*DIM + gt] = acc;
            }
            outT[(size_t)gt*N_NODES + n] = acc;
        }
        GROUP_BAR(g);   // protect sadj/sal reuse next iter
    }
}

// ---------------- phase: fused stats + KDE density + cdf + quantiles ----------------
__device__ void densq_phase(const float* __restrict__ pw, int b, int w, int lane, char* smem){
    int u = w*NBLK + b;           // warp-unit id
    if (u >= NRG*DIM) return;     // warps 11..15 idle
    int rg = u >> 7, d = u & 127;
    int ro = rg >> 2, g = rg & 3;
    const float* baseT = (ro==0) ? g_xT : (ro==1) ? g_c1T : g_c2T;
    float2* sab = (float2*)(smem + w*4096);   // 512 float2 per warp slot
    const float* row = baseT + (size_t)d*N_NODES + g*NGR;

    float v[16];
    float mn=1e30f, mx=-1e30f, s1=0.f, s2=0.f;
    #pragma unroll
    for (int i=0;i<16;i++){
        float x = row[i*32 + lane];
        v[i] = x;
        mn = fminf(mn,x); mx = fmaxf(mx,x);
        s1 += x; s2 = fmaf(x,x,s2);
    }
    #pragma unroll
    for (int o=16;o;o>>=1){
        mn = fminf(mn, __shfl_xor_sync(0xffffffffu,mn,o));
        mx = fmaxf(mx, __shfl_xor_sync(0xffffffffu,mx,o));
        s1 += __shfl_xor_sync(0xffffffffu,s1,o);
        s2 += __shfl_xor_sync(0xffffffffu,s2,o);
    }
    float mean = s1*(1.f/512.f);
    float var  = fmaxf(s2*(1.f/512.f) - mean*mean, 0.f);
    float stdv = sqrtf(var) + 3.3333333e-9f;
    float h    = 0.30440506f*stdv;                   // 1.06*512^-0.2
    float c2   = -0.72134752f/(h*h);                 // -0.5*log2(e)/h^2
    float mnA = mn - 1e-6f, mxA = mx + 1e-6f;
    float step = (mxA - mnA)*(1.f/499.f);
    float mid  = 0.5f*(mnA + mxA);
    if (lane==0) g_pool[rg*DIM + d] = pw[0]*mean + pw[1]*mx;

    #pragma unroll
    for (int i=0;i<16;i++){
        float xc = v[i] - mid;
        sab[i*32 + lane] = make_float2(c2*xc*xc, -2.f*c2*xc);
    }
    __syncwarp();

    float mnc = mnA - mid;
    float g0  = fmaf((float)(lane*16), step, mnc);
    float q0  = c2*g0*g0;
    float K1  = 2.f*c2*step, K2 = c2*step*step;
    float hR  = fmaf(K1, g0, K2);
    float t1  = ex2(2.f*K2);
    float t2  = t1*t1;
    float sc  = t2*t2;
    ull s2p   = pk2(sc, sc);
    ull acc2[8];
    #pragma unroll
    for (int k=0;k<8;k++) acc2[k] = 0ull;
    for (int n=0;n<512;n++){
        float2 abv = sab[n];
        float QA  = fmaf(abv.y, g0, q0) + abv.x;
        float Ra  = fmaf(abv.y, step, hR);
        float eA  = ex2(QA);
        float rho = ex2(Ra);
        float eB  = eA*rho;
        float rA  = rho*rho*t1;
        float rB  = rA*t2;
        ull e2 = pk2(eA, eB);
        ull r2 = pk2(rA, rB);
        acc2[0] = add2(acc2[0], e2);
        #pragma unroll
        for (int k=1;k<8;k++){
            e2 = mul2(e2, r2);
            r2 = mul2(r2, s2p);
            acc2[k] = add2(acc2[k], e2);
        }
    }
    float dens[16];
    #pragma unroll
    for (int k=0;k<8;k++) up2(dens[2*k], dens[2*k+1], acc2[k]);
    int pbase = lane*16;
    #pragma unroll
    for (int j=0;j<16;j++) if (pbase + j >= GRID_PTS) dens[j] = 0.f;
    float cdfl[16];
    float run = 0.f;
    #pragma unroll
    for (int j=0;j<16;j++){ run += dens[j]; cdfl[j] = run; }
    float tot = run, xs = run;
    for (int o=1;o<32;o<<=1){ float t_=__shfl_up_sync(0xffffffffu,xs,o); if (lane>=o) xs+=t_; }
    float basev = xs - tot;
    #pragma unroll
    for (int j=0;j<16;j++) cdfl[j] += basev;
    float total = __shfl_sync(0xffffffffu, cdfl[15], 31);
    float invT  = 1.f/fmaxf(total, 1e-8f);
    float gv0 = mnA;
    #pragma unroll
    for (int j=0;j<16;j++) cdfl[j] *= invT;
    for (int q=0;q<NQ;q++){
        float qq = q*(1.f/19.f);
        float sw=0.f, swg=0.f;
        #pragma unroll
        for (int j=0;j<16;j++){
            int p = pbase + j;
            if (p < GRID_PTS){
                float dist = fabsf(cdfl[j] - qq);
                float wgt = __fdividef(1.f, 1.f + __expf(100.f*dist));
                sw += wgt;
                swg = fmaf(wgt, fmaf((float)p, step, gv0), swg);
            }
        }
        #pragma unroll
        for (int o=16;o;o>>=1){ sw  += __shfl_xor_sync(0xffffffffu,sw,o);
                                swg += __shfl_xor_sync(0xffffffffu,swg,o); }
        if (lane==0) g_kf[rg*2560 + d*NQ + q] = swg/(sw + 1e-8f);
    }
}

// ---------------- the single persistent kernel ----------------
__global__ void __launch_bounds__(NTHR, 1) k_mega(
    const float* __restrict__ x, const int* __restrict__ ei,
    const float* W0, const float* as0, const float* ad0, const float* b0,
    const float* W1, const float* as1, const float* ad1, const float* b1,
    const float* lpW0, const float* lpb0, const float* lpW1, const float* lpb1,
    const float* lpW2, const float* lpb2,
    const float* kW0, const float* kb0, const float* kW1, const float* kb1,
    const float* kW2, const float* kb2,
    const float* pw, const float* beta, const float* h0, float* out)
{
    __shared__ __align__(16) char smem[45056];   // union across phases (11 densq slots)
    int b = blockIdx.x, tid = threadIdx.x;
    int w = tid>>5, lane = tid&31;

    // ---- P0: zero acc/done + fill adjacency + transpose x + lin0 ----
    if (b == 0){
        if (tid < NGRAPH*32) g_acc[tid] = 0.f;
        if (tid == NGRAPH*32) g_done = 0;
    }
    {
        int e = b*NTHR + tid;
        if (e < NEDGE){
            int d = ei[NEDGE+e];
            int pos = atomicAdd(&g_cursor[d], 1);
            if (pos < DEGCAP) g_adjB[d*DEGCAP + pos] = ei[e];
        }
    }
    {
        float (*tile)[129] = (float(*)[129])smem;
        bool doT = (b < 64);
        int n0 = b*32;
        #pragma unroll
        for (int i=0;i<8;i++){
            int idx = tid + i*NTHR;
            int nn = idx>>7, d = idx&127;
            if (doT) tile[nn][d] = x[(size_t)(n0+nn)*DIM + d];
        }
        __syncthreads();
        #pragma unroll
        for (int i=0;i<8;i++){
            int idx = tid + i*NTHR;
            int d = idx>>5, nn = idx&31;
            if (doT) g_xT[(size_t)d*N_NODES + n0 + nn] = tile[nn][d];
        }
        __syncthreads();
    }
    lin_phase(x, W0, as0, ad0, b, tid, smem);
    grid_sync();

    // ---- P1: att layer 0 ----
    att_phase(b0, 0, b, tid, smem);
    grid_sync();

    // ---- P2: lin layer 1 ----
    lin_phase(g_cur1, W1, as1, ad1, b, tid, smem);
    grid_sync();

    // ---- P3: att layer 1 ----
    att_phase(b1, 1, b, tid, smem);
    grid_sync();

    // ---- P4: all 1536 density+quantile units ----
    densq_phase(pw, b, w, lane, smem);
    grid_sync();

    // ---- P5: cursor re-zero (for next replay) + projections + final ----
    {
        int idx = b*NTHR + tid;
        if (idx < N_NODES) g_cursor[idx] = 0;
    }
    if (b < NRG){
        int rg = b, g = rg&3, ro = rg>>2;
        const float* lpW = (ro==0)?lpW0:(ro==1)?lpW1:lpW2;
        const float* lpb = (ro==0)?lpb0:(ro==1)?lpb1:lpb2;
        const float* kW  = (ro==0)?kW0 :(ro==1)?kW1 :kW2;
        const float* kb  = (ro==0)?kb0 :(ro==1)?kb1 :kb2;
        float* r1  = (float*)smem;
        float* r2s = r1 + 256;
        int*   slast = (int*)(smem + 2048);
        int o = tid&31, seg = tid>>5;
        float kp = 0.f, hp = 0.f;
        if (tid < 256){
            const float* kf = &g_kf[rg*2560];
            for (int i=seg*320; i<seg*320+320; i++)
                kp = fmaf(kf[i], kW[i*32 + o], kp);
            const float* wp = &g_pool[rg*DIM];
            for (int dd=seg*16; dd<seg*16+16; dd++)
                hp = fmaf(wp[dd], lpW[dd*32 + o], hp);
            r1[tid] = kp; r2s[tid] = hp;
        }
        __syncthreads();
        if (tid < 32){
            float ks=0.f, hs=0.f;
            #pragma unroll
            for (int s=0;s<8;s++){ ks += r1[tid + s*32]; hs += r2s[tid + s*32]; }
            float val = (ks + kb[tid]) + (hs + lpb[tid]);
            atomicAdd(&g_acc[g*32 + tid], val*(1.f/3.f));
        }
        __threadfence();
        __syncthreads();
        if (tid == 0){
            int prev = atomicAdd(&g_done, 1);
            *slast = (prev == NRG-1);
        }
        __syncthreads();
        if (*slast && tid < 128){
            __threadfence();
            int gg = tid>>5, oo = tid&31;
            float vv = g_acc[gg*32 + oo]*beta[oo];
            #pragma unroll
            for (int ofs=16; ofs; ofs>>=1) vv += __shfl_xor_sync(0xffffffffu, vv, ofs);
            if (oo==0) out[gg] = vv + h0[0];
        }
    }
}

// ---------------- launch: ONE kernel ----------------
extern "C" void kernel_launch(void* const* d_in, const int* in_sizes, int n_in,
                              void* d_out, int out_size){
    const float* x   = (const float*)d_in[0];
    const int*   ei  = (const int*)d_in[1];
    const float* W0  = (const float*)d_in[3];
    const float* as0 = (const float*)d_in[4];
    const float* ad0 = (const float*)d_in[5];
    const float* b0  = (const float*)d_in[6];
    const float* W1  = (const float*)d_in[7];
    const float* as1 = (const float*)d_in[8];
    const float* ad1 = (const float*)d_in[9];
    const float* b1  = (const float*)d_in[10];
    const float* lpW0=(const float*)d_in[11]; const float* lpb0=(const float*)d_in[12];
    const float* lpW1=(const float*)d_in[13]; const float* lpb1=(const float*)d_in[14];
    const float* lpW2=(const float*)d_in[15]; const float* lpb2=(const float*)d_in[16];
    const float* kW0 =(const float*)d_in[17]; const float* kb0 =(const float*)d_in[18];
    const float* kW1 =(const float*)d_in[19]; const float* kb1 =(const float*)d_in[20];
    const float* kW2 =(const float*)d_in[21]; const float* kb2 =(const float*)d_in[22];
    const float* poolw=(const float*)d_in[23];
    const float* beta =(const float*)d_in[24];
    const float* h0   =(const float*)d_in[25];
    float* out = (float*)d_out;

    k_mega<<<NBLK, NTHR>>>(x, ei, W0, as0, ad0, b0, W1, as1, ad1, b1,
                           lpW0, lpb0, lpW1, lpb1, lpW2, lpb2,
                           kW0, kb0, kW1, kb1, kW2, kb2,
                           poolw, beta, h0, out);
}

// round 8
// speedup vs baseline: 1.4190x; 1.1142x over previous
#include <cuda_runtime.h>

#define N_NODES 2048
#define NGR 512
#define NGRAPH 4
#define NEDGE 32768
#define DIM 128
#define HEADS 4
#define GRID_PTS 500
#define NQ 20
#define NRG 12
#define DEGCAP 64
#define NBLK 148
#define NTHR 512

typedef unsigned long long ull;

__device__ float g_xh[N_NODES*DIM];
__device__ float g_als[N_NODES*HEADS];
__device__ float g_ald[N_NODES*HEADS];
__device__ float g_cur1[N_NODES*DIM];
__device__ float g_xT [DIM*N_NODES];
__device__ float g_c1T[DIM*N_NODES];
__device__ float g_c2T[DIM*N_NODES];
__device__ int   g_cursor[N_NODES];
__device__ int   g_adjB[N_NODES*DEGCAP];
__device__ float g_pool[NRG*DIM];
__device__ float g_kf[NRG*DIM*NQ];
__device__ float g_acc[NGRAPH*32];
__device__ int   g_done;
__device__ unsigned g_barCnt;
__device__ volatile unsigned g_barGen;

__device__ __forceinline__ float ex2(float x){
    float y; asm("ex2.approx.ftz.f32 %0, %1;" : "=f"(y) : "f"(x)); return y;
}
__device__ __forceinline__ float rcpf(float x){
    float y; asm("rcp.approx.ftz.f32 %0, %1;" : "=f"(y) : "f"(x)); return y;
}
__device__ __forceinline__ ull pk2(float lo, float hi){
    ull o; asm("mov.b64 %0, {%1, %2};" : "=l"(o) : "f"(lo), "f"(hi)); return o;
}
__device__ __forceinline__ void up2(float& lo, float& hi, ull v){
    asm("mov.b64 {%0, %1}, %2;" : "=f"(lo), "=f"(hi) : "l"(v));
}
__device__ __forceinline__ ull mul2(ull a, ull b){
    ull o; asm("mul.rn.f32x2 %0, %1, %2;" : "=l"(o) : "l"(a), "l"(b)); return o;
}
__device__ __forceinline__ ull add2(ull a, ull b){
    ull o; asm("add.rn.f32x2 %0, %1, %2;" : "=l"(o) : "l"(a), "l"(b)); return o;
}

__device__ __forceinline__ void grid_sync(){
    __syncthreads();
    if (threadIdx.x == 0){
        __threadfence();
        unsigned gen = g_barGen;
        if (atomicAdd(&g_barCnt, 1u) == (unsigned)(NBLK-1)){
            atomicExch(&g_barCnt, 0u);
            __threadfence();
            g_barGen = gen + 1u;
        } else {
            while (g_barGen == gen) __nanosleep(32);
        }
        __threadfence();
    }
    __syncthreads();
}

#define GROUP_BAR(gid) asm volatile("bar.sync %0, %1;" :: "r"((gid)+4), "r"(128) : "memory")

__device__ void lin_phase(const float* __restrict__ cur,
                          const float* __restrict__ W,
                          const float* __restrict__ as_,
                          const float* __restrict__ ad_,
                          int b, int tid, char* smem){
    int g = tid>>7, gt = tid&127;
    int tI = g*NBLK + b;
    bool act = (tI < N_NODES/8);
    float (*srow)[128] = (float(*)[128])(smem + g*4096);
    int n0 = tI*8;
    if (act){
        #pragma unroll
        for (int i=0;i<8;i++){
            int idx = gt + i*128;
            srow[idx>>7][idx&127] = cur[(size_t)n0*DIM + idx];
        }
    }
    GROUP_BAR(g);
    if (act){
        float acc[8] = {0,0,0,0,0,0,0,0};
        #pragma unroll 4
        for (int k4=0;k4<32;k4++){
            float w0 = W[(k4*4+0)*DIM + gt];
            float w1 = W[(k4*4+1)*DIM + gt];
            float w2 = W[(k4*4+2)*DIM + gt];
            float w3 = W[(k4*4+3)*DIM + gt];
            #pragma unroll
            for (int j=0;j<8;j++){
                float4 sv = *(const float4*)&srow[j][k4*4];
                acc[j] = fmaf(sv.x, w0, acc[j]);
                acc[j] = fmaf(sv.y, w1, acc[j]);
                acc[j] = fmaf(sv.z, w2, acc[j]);
                acc[j] = fmaf(sv.w, w3, acc[j]);
            }
        }
        int hw = gt>>5;
        float a_s = as_[gt], a_d = ad_[gt];
        #pragma unroll
        for (int j=0;j<8;j++){
            g_xh[(size_t)(n0+j)*DIM + gt] = acc[j];
            float ps = acc[j]*a_s, pd = acc[j]*a_d;
            #pragma unroll
            for (int o=16;o;o>>=1){
                ps += __shfl_xor_sync(0xffffffffu, ps, o);
                pd += __shfl_xor_sync(0xffffffffu, pd, o);
            }
            if ((gt&31)==0){
                g_als[(n0+j)*HEADS + hw] = ps;
                g_ald[(n0+j)*HEADS + hw] = pd;
            }
        }
    }
}

__device__ void att_phase(const float* __restrict__ bias, int layer,
                          int b, int tid, char* smem){
    int g = tid>>7, gt = tid&127;
    int w4 = gt>>5, lane = gt&31;
    char* base = smem + g*1408;
    int* sadj = (int*)base;
    float (*sal)[68] = (float(*)[68])(base + 272);
    float* outT = layer ? g_c2T : g_c1T;
    float bi = bias[gt];
    for (int iter=0; iter<4; iter++){
        int n = iter*592 + b*4 + g;
        bool act = (n < N_NODES);
        int deg = 0, cnt = 1;
        if (act){
            deg = g_cursor[n]; if (deg > DEGCAP) deg = DEGCAP;
            cnt = deg + 1;
            if (gt < cnt) sadj[gt] = (gt < deg) ? g_adjB[n*DEGCAP + gt] : n;
        }
        GROUP_BAR(g);
        if (act){
            float aldn = g_ald[n*HEADS + w4];
            int i0 = lane, i1 = lane+32, i2 = lane+64;
            float z0=-1e30f, z1=-1e30f, z2=-1e30f;
            if (i0 < cnt){ float z = g_als[sadj[i0]*HEADS+w4] + aldn; z0 = (z>0.f)?z:0.2f*z; }
            if (i1 < cnt){ float z = g_als[sadj[i1]*HEADS+w4] + aldn; z1 = (z>0.f)?z:0.2f*z; }
            if (i2 < cnt){ float z = g_als[sadj[i2]*HEADS+w4] + aldn; z2 = (z>0.f)?z:0.2f*z; }
            float m = fmaxf(z0, fmaxf(z1, z2));
            #pragma unroll
            for (int o=16;o;o>>=1) m = fmaxf(m, __shfl_xor_sync(0xffffffffu,m,o));
            float e0 = (i0<cnt) ? __expf(z0-m) : 0.f;
            float e1 = (i1<cnt) ? __expf(z1-m) : 0.f;
            float e2 = (i2<cnt) ? __expf(z2-m) : 0.f;
            if (i0<cnt) sal[w4][i0] = e0;
            if (i1<cnt) sal[w4][i1] = e1;
            if (i2<cnt) sal[w4][i2] = e2;
            float sum = e0 + e1 + e2;
            #pragma unroll
            for (int o=16;o;o>>=1) sum += __shfl_xor_sync(0xffffffffu,sum,o);
            float inv = 1.f/(sum + 1e-16f);
            __syncwarp();
            float acc = 0.f;
            int i = 0;
            for (; i+8 <= cnt; i += 8){
                float x0=g_xh[(size_t)sadj[i  ]*DIM+gt], x1=g_xh[(size_t)sadj[i+1]*DIM+gt];
                float x2=g_xh[(size_t)sadj[i+2]*DIM+gt], x3=g_xh[(size_t)sadj[i+3]*DIM+gt];
                float x4=g_xh[(size_t)sadj[i+4]*DIM+gt], x5=g_xh[(size_t)sadj[i+5]*DIM+gt];
                float x6=g_xh[(size_t)sadj[i+6]*DIM+gt], x7=g_xh[(size_t)sadj[i+7]*DIM+gt];
                acc = fmaf(sal[w4][i  ],x0,acc); acc = fmaf(sal[w4][i+1],x1,acc);
                acc = fmaf(sal[w4][i+2],x2,acc); acc = fmaf(sal[w4][i+3],x3,acc);
                acc = fmaf(sal[w4][i+4],x4,acc); acc = fmaf(sal[w4][i+5],x5,acc);
                acc = fmaf(sal[w4][i+6],x6,acc); acc = fmaf(sal[w4][i+7],x7,acc);
            }
            for (; i < cnt; i++)
                acc = fmaf(sal[w4][i], g_xh[(size_t)sadj[i]*DIM+gt], acc);
            acc = fmaf(acc, inv, bi);
            if (layer==0){
                acc = fmaxf(acc, 0.f);
                g_cur1[(size_t)n*DIM + gt] = acc;
            }
            outT[(size_t)gt*N_NODES + n] = acc;
        }
        GROUP_BAR(g);
    }
}

__device__ void densq_phase(const float* __restrict__ pw, int b, int w, int lane, char* smem){
    int u = w*NBLK + b;
    if (u >= NRG*DIM) return;
    int rg = u >> 7, d = u & 127;
    int ro = rg >> 2, g = rg & 3;
    const float* baseT = (ro==0) ? g_xT : (ro==1) ? g_c1T : g_c2T;
    float2* sab = (float2*)(smem + w*4096);
    const float* row = baseT + (size_t)d*N_NODES + g*NGR;

    float v[16];
    float mn=1e30f, mx=-1e30f, s1=0.f, s2=0.f;
    #pragma unroll
    for (int i=0;i<16;i++){
        float x = row[i*32 + lane];
        v[i] = x;
        mn = fminf(mn,x); mx = fmaxf(mx,x);
        s1 += x; s2 = fmaf(x,x,s2);
    }
    #pragma unroll
    for (int o=16;o;o>>=1){
        mn = fminf(mn, __shfl_xor_sync(0xffffffffu,mn,o));
        mx = fmaxf(mx, __shfl_xor_sync(0xffffffffu,mx,o));
        s1 += __shfl_xor_sync(0xffffffffu,s1,o);
        s2 += __shfl_xor_sync(0xffffffffu,s2,o);
    }
    float mean = s1*(1.f/512.f);
    float var  = fmaxf(s2*(1.f/512.f) - mean*mean, 0.f);
    float stdv = sqrtf(var) + 3.3333333e-9f;
    float h    = 0.30440506f*stdv;
    float c2   = -0.72134752f/(h*h);
    float mnA = mn - 1e-6f, mxA = mx + 1e-6f;
    float step = (mxA - mnA)*(1.f/499.f);
    float mid  = 0.5f*(mnA + mxA);
    if (lane==0) g_pool[rg*DIM + d] = pw[0]*mean + pw[1]*mx;

    #pragma unroll
    for (int i=0;i<16;i++){
        float xc = v[i] - mid;
        sab[i*32 + lane] = make_float2(c2*xc*xc, -2.f*c2*xc);
    }
    __syncwarp();

    float mnc = mnA - mid;
    float g0  = fmaf((float)(lane*16), step, mnc);
    float q0  = c2*g0*g0;
    float K1  = 2.f*c2*step, K2 = c2*step*step;
    float hR  = fmaf(K1, g0, K2);
    float t1  = ex2(2.f*K2);
    float t2  = t1*t1;
    float sc  = t2*t2;                 // 2^{8 K2}
    ull acc2[8];
    #pragma unroll
    for (int k=0;k<8;k++) acc2[k] = 0ull;
    // e^{(k)} = e0 * r0^k ; node-independent sc^{k(k-1)/2} applied at epilogue
    for (int n=0;n<512;n++){
        float2 abv = sab[n];
        float QA  = fmaf(abv.y, g0, q0) + abv.x;
        float Ra  = fmaf(abv.y, step, hR);
        float eA  = ex2(QA);
        float rho = ex2(Ra);
        float eB  = eA*rho;
        float rA  = rho*rho*t1;
        float rB  = rA*t2;
        ull e2 = pk2(eA, eB);
        ull r2 = pk2(rA, rB);
        acc2[0] = add2(acc2[0], e2);
        #pragma unroll
        for (int k=1;k<8;k++){
            e2 = mul2(e2, r2);
            acc2[k] = add2(acc2[k], e2);
        }
    }
    float dens[16];
    {
        float ck = 1.f, pk = 1.f;      // ck = sc^{k(k-1)/2}, pk = sc^k
        #pragma unroll
        for (int k=0;k<8;k++){
            float lo, hi; up2(lo, hi, acc2[k]);
            dens[2*k]   = lo*ck;
            dens[2*k+1] = hi*ck;
            ck *= pk;                  // C_{k+1} = C_k * sc^k
            pk *= sc;
        }
    }
    int pbase = lane*16;
    #pragma unroll
    for (int j=0;j<16;j++) if (pbase + j >= GRID_PTS) dens[j] = 0.f;
    float cdfl[16];
    float run = 0.f;
    #pragma unroll
    for (int j=0;j<16;j++){ run += dens[j]; cdfl[j] = run; }
    float tot = run, xs = run;
    for (int o=1;o<32;o<<=1){ float t_=__shfl_up_sync(0xffffffffu,xs,o); if (lane>=o) xs+=t_; }
    float basev = xs - tot;
    #pragma unroll
    for (int j=0;j<16;j++) cdfl[j] += basev;
    float total = __shfl_sync(0xffffffffu, cdfl[15], 31);
    float invT  = 1.f/fmaxf(total, 1e-8f);
    #pragma unroll
    for (int j=0;j<16;j++) cdfl[j] *= invT;
    float gpv[16];
    #pragma unroll
    for (int j=0;j<16;j++) gpv[j] = fmaf((float)(pbase+j), step, mnA);
    for (int q=0;q<NQ;q++){
        float qq = q*(1.f/19.f);
        float sw=0.f, swg=0.f;
        #pragma unroll
        for (int j=0;j<16;j++){
            int p = pbase + j;
            if (p < GRID_PTS){
                float dist = fabsf(cdfl[j] - qq);
                float wgt = rcpf(1.f + ex2(144.269504f*dist));
                sw += wgt;
                swg = fmaf(wgt, gpv[j], swg);
            }
        }
        #pragma unroll
        for (int o=16;o;o>>=1){ sw  += __shfl_xor_sync(0xffffffffu,sw,o);
                                swg += __shfl_xor_sync(0xffffffffu,swg,o); }
        if (lane==0) g_kf[rg*2560 + d*NQ + q] = swg/(sw + 1e-8f);
    }
}

__global__ void __launch_bounds__(NTHR, 1) k_mega(
    const float* __restrict__ x, const int* __restrict__ ei,
    const float* W0, const float* as0, const float* ad0, const float* b0,
    const float* W1, const float* as1, const float* ad1, const float* b1,
    const float* lpW0, const float* lpb0, const float* lpW1, const float* lpb1,
    const float* lpW2, const float* lpb2,
    const float* kW0, const float* kb0, const float* kW1, const float* kb1,
    const float* kW2, const float* kb2,
    const float* pw, const float* beta, const float* h0, float* out)
{
    __shared__ __align__(16) char smem[45056];
    int b = blockIdx.x, tid = threadIdx.x;
    int w = tid>>5, lane = tid&31;

    if (b == 0){
        if (tid < NGRAPH*32) g_acc[tid] = 0.f;
        if (tid == NGRAPH*32) g_done = 0;
    }
    {
        int e = b*NTHR + tid;
        if (e < NEDGE){
            int d = ei[NEDGE+e];
            int pos = atomicAdd(&g_cursor[d], 1);
            if (pos < DEGCAP) g_adjB[d*DEGCAP + pos] = ei[e];
        }
    }
    {
        float (*tile)[129] = (float(*)[129])smem;
        bool doT = (b < 64);
        int n0 = b*32;
        #pragma unroll
        for (int i=0;i<8;i++){
            int idx = tid + i*NTHR;
            int nn = idx>>7, d = idx&127;
            if (doT) tile[nn][d] = x[(size_t)(n0+nn)*DIM + d];
        }
        __syncthreads();
        #pragma unroll
        for (int i=0;i<8;i++){
            int idx = tid + i*NTHR;
            int d = idx>>5, nn = idx&31;
            if (doT) g_xT[(size_t)d*N_NODES + n0 + nn] = tile[nn][d];
        }
        __syncthreads();
    }
    lin_phase(x, W0, as0, ad0, b, tid, smem);
    grid_sync();

    att_phase(b0, 0, b, tid, smem);
    grid_sync();

    lin_phase(g_cur1, W1, as1, ad1, b, tid, smem);
    grid_sync();

    att_phase(b1, 1, b, tid, smem);
    grid_sync();

    densq_phase(pw, b, w, lane, smem);
    grid_sync();

    {
        int idx = b*NTHR + tid;
        if (idx < N_NODES) g_cursor[idx] = 0;
    }
    if (b < NRG){
        int rg = b, g = rg&3, ro = rg>>2;
        const float* lpW = (ro==0)?lpW0:(ro==1)?lpW1:lpW2;
        const float* lpb = (ro==0)?lpb0:(ro==1)?lpb1:lpb2;
        const float* kW  = (ro==0)?kW0 :(ro==1)?kW1 :kW2;
        const float* kb  = (ro==0)?kb0 :(ro==1)?kb1 :kb2;
        float* r1  = (float*)smem;
        float* r2s = r1 + 256;
        int*   slast = (int*)(smem + 2048);
        int o = tid&31, seg = tid>>5;
        float kp = 0.f, hp = 0.f;
        if (tid < 256){
            const float* kf = &g_kf[rg*2560];
            for (int i=seg*320; i<seg*320+320; i++)
                kp = fmaf(kf[i], kW[i*32 + o], kp);
            const float* wp = &g_pool[rg*DIM];
            for (int dd=seg*16; dd<seg*16+16; dd++)
                hp = fmaf(wp[dd], lpW[dd*32 + o], hp);
            r1[tid] = kp; r2s[tid] = hp;
        }
        __syncthreads();
        if (tid < 32){
            float ks=0.f, hs=0.f;
            #pragma unroll
            for (int s=0;s<8;s++){ ks += r1[tid + s*32]; hs += r2s[tid + s*32]; }
            float val = (ks + kb[tid]) + (hs + lpb[tid]);
            atomicAdd(&g_acc[g*32 + tid], val*(1.f/3.f));
        }
        __threadfence();
        __syncthreads();
        if (tid == 0){
            int prev = atomicAdd(&g_done, 1);
            *slast = (prev == NRG-1);
        }
        __syncthreads();
        if (*slast && tid < 128){
            __threadfence();
            int gg = tid>>5, oo = tid&31;
            float vv = g_acc[gg*32 + oo]*beta[oo];
            #pragma unroll
            for (int ofs=16; ofs; ofs>>=1) vv += __shfl_xor_sync(0xffffffffu, vv, ofs);
            if (oo==0) out[gg] = vv + h0[0];
        }
    }
}

extern "C" void kernel_launch(void* const* d_in, const int* in_sizes, int n_in,
                              void* d_out, int out_size){
    const float* x   = (const float*)d_in[0];
    const int*   ei  = (const int*)d_in[1];
    const float* W0  = (const float*)d_in[3];
    const float* as0 = (const float*)d_in[4];
    const float* ad0 = (const float*)d_in[5];
    const float* b0  = (const float*)d_in[6];
    const float* W1  = (const float*)d_in[7];
    const float* as1 = (const float*)d_in[8];
    const float* ad1 = (const float*)d_in[9];
    const float* b1  = (const float*)d_in[10];
    const float* lpW0=(const float*)d_in[11]; const float* lpb0=(const float*)d_in[12];
    const float* lpW1=(const float*)d_in[13]; const float* lpb1=(const float*)d_in[14];
    const float* lpW2=(const float*)d_in[15]; const float* lpb2=(const float*)d_in[16];
    const float* kW0 =(const float*)d_in[17]; const float* kb0 =(const float*)d_in[18];
    const float* kW1 =(const float*)d_in[19]; const float* kb1 =(const float*)d_in[20];
    const float* kW2 =(const float*)d_in[21]; const float* kb2 =(const float*)d_in[22];
    const float* poolw=(const float*)d_in[23];
    const float* beta =(const float*)d_in[24];
    const float* h0   =(const float*)d_in[25];
    float* out = (float*)d_out;

    k_mega<<<NBLK, NTHR>>>(x, ei, W0, as0, ad0, b0, W1, as1, ad1, b1,
                           lpW0, lpb0, lpW1, lpb1, lpW2, lpb2,
                           kW0, kb0, kW1, kb1, kW2, kb2,
                           poolw, beta, h0, out);
}

// round 10
// speedup vs baseline: 1.6264x; 1.1462x over previous
#include <cuda_runtime.h>

#define N_NODES 2048
#define NGR 512
#define NGRAPH 4
#define NEDGE 32768
#define DIM 128
#define HEADS 4
#define GRID_PTS 500
#define NQ 20
#define NRG 12
#define DEGCAP 64
#define NBLK 148
#define NTHR 512

typedef unsigned long long ull;

__device__ float g_xh[N_NODES*DIM];
__device__ float g_als[N_NODES*HEADS];
__device__ float g_ald[N_NODES*HEADS];
__device__ float g_cur1[N_NODES*DIM];
__device__ float g_xT [DIM*N_NODES];
__device__ float g_c1T[DIM*N_NODES];
__device__ float g_c2T[DIM*N_NODES];
__device__ int   g_cursor[N_NODES];
__device__ int   g_adjB[N_NODES*DEGCAP];
__device__ float g_pool[NRG*DIM];
__device__ float g_kf[NRG*DIM*NQ];
__device__ float g_acc[NGRAPH*32];
__device__ int   g_done;
__device__ unsigned g_barCnt;
__device__ volatile unsigned g_barGen;

__device__ __forceinline__ float ex2(float x){
    float y; asm("ex2.approx.ftz.f32 %0, %1;" : "=f"(y) : "f"(x)); return y;
}
__device__ __forceinline__ float rcpf(float x){
    float y; asm("rcp.approx.ftz.f32 %0, %1;" : "=f"(y) : "f"(x)); return y;
}
__device__ __forceinline__ ull pk2(float lo, float hi){
    ull o; asm("mov.b64 %0, {%1, %2};" : "=l"(o) : "f"(lo), "f"(hi)); return o;
}
__device__ __forceinline__ void up2(float& lo, float& hi, ull v){
    asm("mov.b64 {%0, %1}, %2;" : "=f"(lo), "=f"(hi) : "l"(v));
}
__device__ __forceinline__ ull mul2(ull a, ull b){
    ull o; asm("mul.rn.f32x2 %0, %1, %2;" : "=l"(o) : "l"(a), "l"(b)); return o;
}
__device__ __forceinline__ ull add2(ull a, ull b){
    ull o; asm("add.rn.f32x2 %0, %1, %2;" : "=l"(o) : "l"(a), "l"(b)); return o;
}

__device__ __forceinline__ void grid_sync(){
    __syncthreads();
    if (threadIdx.x == 0){
        __threadfence();
        unsigned gen = g_barGen;
        if (atomicAdd(&g_barCnt, 1u) == (unsigned)(NBLK-1)){
            atomicExch(&g_barCnt, 0u);
            __threadfence();
            g_barGen = gen + 1u;
        } else {
            while (g_barGen == gen) __nanosleep(32);
        }
        __threadfence();
    }
    __syncthreads();
}

#define GROUP_BAR(gid) asm volatile("bar.sync %0, %1;" :: "r"((gid)+4), "r"(128) : "memory")

__device__ void lin_phase(const float* __restrict__ cur,
                          const float* __restrict__ W,
                          const float* __restrict__ as_,
                          const float* __restrict__ ad_,
                          int b, int tid, char* smem){
    int g = tid>>7, gt = tid&127;
    int tI = g*NBLK + b;
    bool act = (tI < N_NODES/8);
    float (*srow)[128] = (float(*)[128])(smem + g*4096);
    int n0 = tI*8;
    if (act){
        #pragma unroll
        for (int i=0;i<8;i++){
            int idx = gt + i*128;
            srow[idx>>7][idx&127] = cur[(size_t)n0*DIM + idx];
        }
    }
    GROUP_BAR(g);
    if (act){
        float acc[8] = {0,0,0,0,0,0,0,0};
        #pragma unroll 4
        for (int k4=0;k4<32;k4++){
            float w0 = W[(k4*4+0)*DIM + gt];
            float w1 = W[(k4*4+1)*DIM + gt];
            float w2 = W[(k4*4+2)*DIM + gt];
            float w3 = W[(k4*4+3)*DIM + gt];
            #pragma unroll
            for (int j=0;j<8;j++){
                float4 sv = *(const float4*)&srow[j][k4*4];
                acc[j] = fmaf(sv.x, w0, acc[j]);
                acc[j] = fmaf(sv.y, w1, acc[j]);
                acc[j] = fmaf(sv.z, w2, acc[j]);
                acc[j] = fmaf(sv.w, w3, acc[j]);
            }
        }
        int hw = gt>>5;
        float a_s = as_[gt], a_d = ad_[gt];
        #pragma unroll
        for (int j=0;j<8;j++){
            g_xh[(size_t)(n0+j)*DIM + gt] = acc[j];
            float ps = acc[j]*a_s, pd = acc[j]*a_d;
            #pragma unroll
            for (int o=16;o;o>>=1){
                ps += __shfl_xor_sync(0xffffffffu, ps, o);
                pd += __shfl_xor_sync(0xffffffffu, pd, o);
            }
            if ((gt&31)==0){
                g_als[(n0+j)*HEADS + hw] = ps;
                g_ald[(n0+j)*HEADS + hw] = pd;
            }
        }
    }
}

// ---- attention: ONE WARP PER NODE, float4 aggregation, no block barriers ----
__device__ void att_phase(const float* __restrict__ bias, int layer,
                          int b, int tid, char* smem){
    int w = tid>>5, lane = tid&31;
    int n = w*NBLK + b;
    if (n < N_NODES){
        float* outT = layer ? g_c2T : g_c1T;
        char* base = smem + w*1376;
        int*   sadj = (int*)base;            // 68 ints
        float* sal  = (float*)(base + 272);  // [4][68] floats
        int deg = g_cursor[n]; if (deg > DEGCAP) deg = DEGCAP;
        int cnt = deg + 1;
        for (int i=lane; i<cnt; i+=32)
            sadj[i] = (i < deg) ? g_adjB[n*DEGCAP + i] : n;
        __syncwarp();
        int h = lane & 3, sub = lane >> 2;
        float aldn = g_ald[n*HEADS + h];
        int nch = (cnt + 7) >> 3;
        float mx = -1e30f;
        for (int c=0;c<nch;c++){
            int i = c*8 + sub;
            if (i < cnt){
                float z = g_als[sadj[i]*HEADS + h] + aldn;
                z = (z>0.f) ? z : 0.2f*z;
                sal[h*68 + i] = z;
                mx = fmaxf(mx, z);
            }
        }
        mx = fmaxf(mx, __shfl_xor_sync(0xffffffffu, mx, 4));
        mx = fmaxf(mx, __shfl_xor_sync(0xffffffffu, mx, 8));
        mx = fmaxf(mx, __shfl_xor_sync(0xffffffffu, mx, 16));
        float sum = 0.f;
        for (int c=0;c<nch;c++){
            int i = c*8 + sub;
            if (i < cnt){
                float e = __expf(sal[h*68+i] - mx);
                sal[h*68+i] = e;
                sum += e;
            }
        }
        sum += __shfl_xor_sync(0xffffffffu, sum, 4);
        sum += __shfl_xor_sync(0xffffffffu, sum, 8);
        sum += __shfl_xor_sync(0xffffffffu, sum, 16);
        float inv = 1.f/(sum + 1e-16f);
        // FIX(R9): aggregation head is lane>>3 but inv was for head lane&3.
        // lane h' (0..3) holds head h' (since h'&3 == h'), so broadcast from it.
        float invA = __shfl_sync(0xffffffffu, inv, lane>>3);
        __syncwarp();
        // aggregation: lane handles dims [lane*4, lane*4+4), head = lane>>3
        const float* salh = sal + (lane>>3)*68;
        float ax=0.f, ay=0.f, az=0.f, aw=0.f;
        int i=0;
        for (; i+4<=cnt; i+=4){
            float a0=salh[i], a1=salh[i+1], a2=salh[i+2], a3=salh[i+3];
            float4 x0 = *(const float4*)&g_xh[(size_t)sadj[i  ]*DIM + lane*4];
            float4 x1 = *(const float4*)&g_xh[(size_t)sadj[i+1]*DIM + lane*4];
            float4 x2 = *(const float4*)&g_xh[(size_t)sadj[i+2]*DIM + lane*4];
            float4 x3 = *(const float4*)&g_xh[(size_t)sadj[i+3]*DIM + lane*4];
            ax=fmaf(a0,x0.x,ax); ay=fmaf(a0,x0.y,ay); az=fmaf(a0,x0.z,az); aw=fmaf(a0,x0.w,aw);
            ax=fmaf(a1,x1.x,ax); ay=fmaf(a1,x1.y,ay); az=fmaf(a1,x1.z,az); aw=fmaf(a1,x1.w,aw);
            ax=fmaf(a2,x2.x,ax); ay=fmaf(a2,x2.y,ay); az=fmaf(a2,x2.z,az); aw=fmaf(a2,x2.w,aw);
            ax=fmaf(a3,x3.x,ax); ay=fmaf(a3,x3.y,ay); az=fmaf(a3,x3.z,az); aw=fmaf(a3,x3.w,aw);
        }
        for (; i<cnt; i++){
            float a0 = salh[i];
            float4 x0 = *(const float4*)&g_xh[(size_t)sadj[i]*DIM + lane*4];
            ax=fmaf(a0,x0.x,ax); ay=fmaf(a0,x0.y,ay); az=fmaf(a0,x0.z,az); aw=fmaf(a0,x0.w,aw);
        }
        float4 bi = *(const float4*)&bias[lane*4];
        ax = fmaf(ax, invA, bi.x); ay = fmaf(ay, invA, bi.y);
        az = fmaf(az, invA, bi.z); aw = fmaf(aw, invA, bi.w);
        if (layer==0){
            ax=fmaxf(ax,0.f); ay=fmaxf(ay,0.f); az=fmaxf(az,0.f); aw=fmaxf(aw,0.f);
            *(float4*)&g_cur1[(size_t)n*DIM + lane*4] = make_float4(ax,ay,az,aw);
        }
        size_t cb = (size_t)(lane*4)*N_NODES + n;
        outT[cb]             = ax;
        outT[cb +   N_NODES] = ay;
        outT[cb + 2*N_NODES] = az;
        outT[cb + 3*N_NODES] = aw;
    }
}

__device__ void densq_phase(const float* __restrict__ pw, int b, int w, int lane, char* smem){
    int u = w*NBLK + b;
    if (u >= NRG*DIM) return;
    int rg = u >> 7, d = u & 127;
    int ro = rg >> 2, g = rg & 3;
    const float* baseT = (ro==0) ? g_xT : (ro==1) ? g_c1T : g_c2T;
    float2* sab = (float2*)(smem + w*4096);
    const float* row = baseT + (size_t)d*N_NODES + g*NGR;

    float v[16];
    float mn=1e30f, mx=-1e30f, s1=0.f, s2=0.f;
    #pragma unroll
    for (int i=0;i<16;i++){
        float x = row[i*32 + lane];
        v[i] = x;
        mn = fminf(mn,x); mx = fmaxf(mx,x);
        s1 += x; s2 = fmaf(x,x,s2);
    }
    #pragma unroll
    for (int o=16;o;o>>=1){
        mn = fminf(mn, __shfl_xor_sync(0xffffffffu,mn,o));
        mx = fmaxf(mx, __shfl_xor_sync(0xffffffffu,mx,o));
        s1 += __shfl_xor_sync(0xffffffffu,s1,o);
        s2 += __shfl_xor_sync(0xffffffffu,s2,o);
    }
    float mean = s1*(1.f/512.f);
    float var  = fmaxf(s2*(1.f/512.f) - mean*mean, 0.f);
    float stdv = sqrtf(var) + 3.3333333e-9f;
    float h    = 0.30440506f*stdv;
    float c2   = -0.72134752f/(h*h);
    float mnA = mn - 1e-6f, mxA = mx + 1e-6f;
    float step = (mxA - mnA)*(1.f/499.f);
    float mid  = 0.5f*(mnA + mxA);
    if (lane==0) g_pool[rg*DIM + d] = pw[0]*mean + pw[1]*mx;

    #pragma unroll
    for (int i=0;i<16;i++){
        float xc = v[i] - mid;
        sab[i*32 + lane] = make_float2(c2*xc*xc, -2.f*c2*xc);
    }
    __syncwarp();

    float mnc = mnA - mid;
    float g0  = fmaf((float)(lane*16), step, mnc);
    float q0  = c2*g0*g0;
    float K1  = 2.f*c2*step, K2 = c2*step*step;
    float hR  = fmaf(K1, g0, K2);
    float t1  = ex2(2.f*K2);
    float t2  = t1*t1;
    float sc  = t2*t2;                 // 2^{8 K2}
    ull acc2[8];
    #pragma unroll
    for (int k=0;k<8;k++) acc2[k] = 0ull;
    for (int n=0;n<512;n++){
        float2 abv = sab[n];
        float QA  = fmaf(abv.y, g0, q0) + abv.x;
        float Ra  = fmaf(abv.y, step, hR);
        float eA  = ex2(QA);
        float rho = ex2(Ra);
        float eB  = eA*rho;
        float rA  = rho*rho*t1;
        float rB  = rA*t2;
        ull e2 = pk2(eA, eB);
        ull r2 = pk2(rA, rB);
        acc2[0] = add2(acc2[0], e2);
        #pragma unroll
        for (int k=1;k<8;k++){
            e2 = mul2(e2, r2);
            acc2[k] = add2(acc2[k], e2);
        }
    }
    float dens[16];
    {
        float ck = 1.f, pk = 1.f;      // ck = sc^{k(k-1)/2}, pk = sc^k
        #pragma unroll
        for (int k=0;k<8;k++){
            float lo, hi; up2(lo, hi, acc2[k]);
            dens[2*k]   = lo*ck;
            dens[2*k+1] = hi*ck;
            ck *= pk;
            pk *= sc;
        }
    }
    int pbase = lane*16;
    #pragma unroll
    for (int j=0;j<16;j++) if (pbase + j >= GRID_PTS) dens[j] = 0.f;
    float cdfl[16];
    float run = 0.f;
    #pragma unroll
    for (int j=0;j<16;j++){ run += dens[j]; cdfl[j] = run; }
    float tot = run, xs = run;
    for (int o=1;o<32;o<<=1){ float t_=__shfl_up_sync(0xffffffffu,xs,o); if (lane>=o) xs+=t_; }
    float basev = xs - tot;
    #pragma unroll
    for (int j=0;j<16;j++) cdfl[j] += basev;
    float total = __shfl_sync(0xffffffffu, cdfl[15], 31);
    float invT  = 1.f/fmaxf(total, 1e-8f);
    #pragma unroll
    for (int j=0;j<16;j++){
        cdfl[j] *= invT;
        if (pbase + j >= GRID_PTS) cdfl[j] = 4e9f;   // sentinel -> wgt == 0
    }
    float gpv[16];
    #pragma unroll
    for (int j=0;j<16;j++) gpv[j] = fmaf((float)(pbase+j), step, mnA);
    for (int q2=0; q2<NQ; q2+=2){
        float qa = q2*(1.f/19.f), qb = (q2+1)*(1.f/19.f);
        float swa=0.f, swga=0.f, swb=0.f, swgb=0.f;
        #pragma unroll
        for (int j=0;j<16;j++){
            float da = fabsf(cdfl[j] - qa);
            float db = fabsf(cdfl[j] - qb);
            float wa = rcpf(1.f + ex2(144.269504f*da));
            float wb = rcpf(1.f + ex2(144.269504f*db));
            swa += wa; swga = fmaf(wa, gpv[j], swga);
            swb += wb; swgb = fmaf(wb, gpv[j], swgb);
        }
        #pragma unroll
        for (int o=16;o;o>>=1){
            swa += __shfl_xor_sync(0xffffffffu,swa,o);
            swga+= __shfl_xor_sync(0xffffffffu,swga,o);
            swb += __shfl_xor_sync(0xffffffffu,swb,o);
            swgb+= __shfl_xor_sync(0xffffffffu,swgb,o);
        }
        if (lane==0){
            g_kf[rg*2560 + d*NQ + q2]   = swga/(swa + 1e-8f);
            g_kf[rg*2560 + d*NQ + q2+1] = swgb/(swb + 1e-8f);
        }
    }
}

__global__ void __launch_bounds__(NTHR, 1) k_mega(
    const float* __restrict__ x, const int* __restrict__ ei,
    const float* W0, const float* as0, const float* ad0, const float* b0,
    const float* W1, const float* as1, const float* ad1, const float* b1,
    const float* lpW0, const float* lpb0, const float* lpW1, const float* lpb1,
    const float* lpW2, const float* lpb2,
    const float* kW0, const float* kb0, const float* kW1, const float* kb1,
    const float* kW2, const float* kb2,
    const float* pw, const float* beta, const float* h0, float* out)
{
    __shared__ __align__(16) char smem[45056];
    int b = blockIdx.x, tid = threadIdx.x;
    int w = tid>>5, lane = tid&31;

    if (b == 0){
        if (tid < NGRAPH*32) g_acc[tid] = 0.f;
        if (tid == NGRAPH*32) g_done = 0;
    }
    {
        int e = b*NTHR + tid;
        if (e < NEDGE){
            int d = ei[NEDGE+e];
            int pos = atomicAdd(&g_cursor[d], 1);
            if (pos < DEGCAP) g_adjB[d*DEGCAP + pos] = ei[e];
        }
    }
    {
        float (*tile)[129] = (float(*)[129])smem;
        bool doT = (b < 64);
        int n0 = b*32;
        #pragma unroll
        for (int i=0;i<8;i++){
            int idx = tid + i*NTHR;
            int nn = idx>>7, d = idx&127;
            if (doT) tile[nn][d] = x[(size_t)(n0+nn)*DIM + d];
        }
        __syncthreads();
        #pragma unroll
        for (int i=0;i<8;i++){
            int idx = tid + i*NTHR;
            int d = idx>>5, nn = idx&31;
            if (doT) g_xT[(size_t)d*N_NODES + n0 + nn] = tile[nn][d];
        }
        __syncthreads();
    }
    lin_phase(x, W0, as0, ad0, b, tid, smem);
    grid_sync();

    att_phase(b0, 0, b, tid, smem);
    grid_sync();

    lin_phase(g_cur1, W1, as1, ad1, b, tid, smem);
    grid_sync();

    att_phase(b1, 1, b, tid, smem);
    grid_sync();

    densq_phase(pw, b, w, lane, smem);
    grid_sync();

    {
        int idx = b*NTHR + tid;
        if (idx < N_NODES) g_cursor[idx] = 0;
    }
    if (b < NRG){
        int rg = b, g = rg&3, ro = rg>>2;
        const float* lpW = (ro==0)?lpW0:(ro==1)?lpW1:lpW2;
        const float* lpb = (ro==0)?lpb0:(ro==1)?lpb1:lpb2;
        const float* kW  = (ro==0)?kW0 :(ro==1)?kW1 :kW2;
        const float* kb  = (ro==0)?kb0 :(ro==1)?kb1 :kb2;
        float* r1  = (float*)smem;
        float* r2s = r1 + 256;
        int*   slast = (int*)(smem + 2048);
        int o = tid&31, seg = tid>>5;
        float kp = 0.f, hp = 0.f;
        if (tid < 256){
            const float* kf = &g_kf[rg*2560];
            for (int i=seg*320; i<seg*320+320; i++)
                kp = fmaf(kf[i], kW[i*32 + o], kp);
            const float* wp = &g_pool[rg*DIM];
            for (int dd=seg*16; dd<seg*16+16; dd++)
                hp = fmaf(wp[dd], lpW[dd*32 + o], hp);
            r1[tid] = kp; r2s[tid] = hp;
        }
        __syncthreads();
        if (tid < 32){
            float ks=0.f, hs=0.f;
            #pragma unroll
            for (int s=0;s<8;s++){ ks += r1[tid + s*32]; hs += r2s[tid + s*32]; }
            float val = (ks + kb[tid]) + (hs + lpb[tid]);
            atomicAdd(&g_acc[g*32 + tid], val*(1.f/3.f));
        }
        __threadfence();
        __syncthreads();
        if (tid == 0){
            int prev = atomicAdd(&g_done, 1);
            *slast = (prev == NRG-1);
        }
        __syncthreads();
        if (*slast && tid < 128){
            __threadfence();
            int gg = tid>>5, oo = tid&31;
            float vv = g_acc[gg*32 + oo]*beta[oo];
            #pragma unroll
            for (int ofs=16; ofs; ofs>>=1) vv += __shfl_xor_sync(0xffffffffu, vv, ofs);
            if (oo==0) out[gg] = vv + h0[0];
        }
    }
}

extern "C" void kernel_launch(void* const* d_in, const int* in_sizes, int n_in,
                              void* d_out, int out_size){
    const float* x   = (const float*)d_in[0];
    const int*   ei  = (const int*)d_in[1];
    const float* W0  = (const float*)d_in[3];
    const float* as0 = (const float*)d_in[4];
    const float* ad0 = (const float*)d_in[5];
    const float* b0  = (const float*)d_in[6];
    const float* W1  = (const float*)d_in[7];
    const float* as1 = (const float*)d_in[8];
    const float* ad1 = (const float*)d_in[9];
    const float* b1  = (const float*)d_in[10];
    const float* lpW0=(const float*)d_in[11]; const float* lpb0=(const float*)d_in[12];
    const float* lpW1=(const float*)d_in[13]; const float* lpb1=(const float*)d_in[14];
    const float* lpW2=(const float*)d_in[15]; const float* lpb2=(const float*)d_in[16];
    const float* kW0 =(const float*)d_in[17]; const float* kb0 =(const float*)d_in[18];
    const float* kW1 =(const float*)d_in[19]; const float* kb1 =(const float*)d_in[20];
    const float* kW2 =(const float*)d_in[21]; const float* kb2 =(const float*)d_in[22];
    const float* poolw=(const float*)d_in[23];
    const float* beta =(const float*)d_in[24];
    const float* h0   =(const float*)d_in[25];
    float* out = (float*)d_out;

    k_mega<<<NBLK, NTHR>>>(x, ei, W0, as0, ad0, b0, W1, as1, ad1, b1,
                           lpW0, lpb0, lpW1, lpb1, lpW2, lpb2,
                           kW0, kb0, kW1, kb1, kW2, kb2,
                           poolw, beta, h0, out);
}